// round 1
// baseline (speedup 1.0000x reference)
#include <cuda_runtime.h>
#include <cuda_bf16.h>
#include <math.h>

// Problem constants
#define BATCH 2
#define C 256
#define HW 3136          // 56*56
#define HEADS 8
#define HD 32
#define EPS 1e-5f
#define C4 (4*C)         // 1024

// ---------------------------------------------------------------------------
// Scratch (device globals; no allocation allowed)
// ---------------------------------------------------------------------------
__device__ float g_s1[C], g_t1[C];          // BN1 folded scale/shift
__device__ float g_s2[C], g_t2[C];          // BN2 folded scale/shift
__device__ float g_wq[C*C], g_wk[C*C], g_wv[C*C];
__device__ float g_bq[C], g_bk[C], g_bv[C];
__device__ float g_wm1[C4*C];
__device__ float g_bm1[C4];
__device__ float g_q[BATCH*C*HW];
__device__ float g_k[BATCH*C*HW];
__device__ float g_v[BATCH*C*HW];
__device__ float g_ao[BATCH*C*HW];
__device__ float g_x2[BATCH*C*HW];
__device__ float g_h[BATCH*C4*HW];

// ---------------------------------------------------------------------------
// BN stats: per-channel mean/var over (B, HW); emit scale s = g*rsqrt(var+eps)
// and shift t = beta - mean*s
// ---------------------------------------------------------------------------
__global__ void bn_stats_kernel(const float* __restrict__ x,
                                const float* __restrict__ gamma,
                                const float* __restrict__ beta,
                                float* __restrict__ s, float* __restrict__ t) {
    int c = blockIdx.x;
    int tid = threadIdx.x;
    float sum = 0.f, sq = 0.f;
    for (int b = 0; b < BATCH; b++) {
        const float* p = x + ((size_t)b * C + c) * HW;
        for (int i = tid; i < HW; i += blockDim.x) {
            float v = p[i];
            sum += v; sq += v * v;
        }
    }
    __shared__ float rs[256], rq[256];
    rs[tid] = sum; rq[tid] = sq;
    __syncthreads();
    for (int off = 128; off > 0; off >>= 1) {
        if (tid < off) { rs[tid] += rs[tid + off]; rq[tid] += rq[tid + off]; }
        __syncthreads();
    }
    if (tid == 0) {
        const float n = (float)(BATCH * HW);
        float mean = rs[0] / n;
        float var  = rq[0] / n - mean * mean;
        float sc = gamma[c] * rsqrtf(var + EPS);
        s[c] = sc;
        t[c] = beta[c] - mean * sc;
    }
}

// ---------------------------------------------------------------------------
// Fold BN into conv weights: wf[o,c] = w[o,c]*s[c]; bf[o] = b[o] + sum_c w[o,c]*t[c]
// grid = M blocks, 256 threads (K==256 here)
// ---------------------------------------------------------------------------
__global__ void fold_kernel(const float* __restrict__ w, const float* __restrict__ bias,
                            const float* __restrict__ s, const float* __restrict__ t,
                            float* __restrict__ wf, float* __restrict__ bf, int K) {
    int o = blockIdx.x;
    int tid = threadIdx.x;
    float acc = 0.f;
    for (int c = tid; c < K; c += blockDim.x) {
        float wv = w[(size_t)o * K + c];
        wf[(size_t)o * K + c] = wv * s[c];
        acc += wv * t[c];
    }
    __shared__ float red[256];
    red[tid] = acc;
    __syncthreads();
    for (int off = 128; off > 0; off >>= 1) {
        if (tid < off) red[tid] += red[tid + off];
        __syncthreads();
    }
    if (tid == 0) bf[o] = bias[o] + red[0];
}

// ---------------------------------------------------------------------------
// Tiled fp32 GEMM: C[b] = A[M,K] * B[b][K,N] + bias (+epilogue)
// BM=128, BN=64, BK=16, 256 threads, microtile 8x4.
// EPI: 0 = plain, 1 = relu, 2 = add residual
// grid = (N/64, M/128, BATCH)
// ---------------------------------------------------------------------------
template<int EPI>
__global__ void __launch_bounds__(256)
gemm_kernel(const float* __restrict__ A, const float* __restrict__ Bm,
            const float* __restrict__ bias, const float* __restrict__ res,
            float* __restrict__ Cout, int M, int K, int N) {
    const int bn = blockIdx.x;
    const int bm = blockIdx.y;
    const int batch = blockIdx.z;
    const float* Bp = Bm + (size_t)batch * K * N;
    float* Cp = Cout + (size_t)batch * M * N;
    const float* Rp = (EPI == 2) ? (res + (size_t)batch * M * N) : nullptr;

    __shared__ float As[16][128];
    __shared__ float Bs[16][64];

    const int tid = threadIdx.x;
    const int tx = tid & 15;        // 0..15  -> columns
    const int ty = tid >> 4;        // 0..15  -> rows
    const int row0 = bm * 128 + ty * 8;
    const int col0 = bn * 64 + tx * 4;

    float acc[8][4];
#pragma unroll
    for (int i = 0; i < 8; i++)
#pragma unroll
        for (int j = 0; j < 4; j++) acc[i][j] = 0.f;

    for (int k0 = 0; k0 < K; k0 += 16) {
        // A tile: 128 rows x 16 k, float4 along k, store transposed
#pragma unroll
        for (int it = 0; it < 2; it++) {
            int li = tid + it * 256;            // 0..511
            int r  = li >> 2;                   // 0..127
            int kk = (li & 3) * 4;              // 0,4,8,12
            float4 v = *(const float4*)&A[(size_t)(bm * 128 + r) * K + k0 + kk];
            As[kk + 0][r] = v.x; As[kk + 1][r] = v.y;
            As[kk + 2][r] = v.z; As[kk + 3][r] = v.w;
        }
        // B tile: 16 k x 64 n, one float4 per thread
        {
            int kk = tid >> 4;                  // 0..15
            int nn = (tid & 15) * 4;
            float4 v = *(const float4*)&Bp[(size_t)(k0 + kk) * N + bn * 64 + nn];
            *(float4*)&Bs[kk][nn] = v;
        }
        __syncthreads();
#pragma unroll
        for (int k = 0; k < 16; k++) {
            float a[8], b[4];
            *(float4*)&a[0] = *(const float4*)&As[k][ty * 8];
            *(float4*)&a[4] = *(const float4*)&As[k][ty * 8 + 4];
            *(float4*)&b[0] = *(const float4*)&Bs[k][tx * 4];
#pragma unroll
            for (int i = 0; i < 8; i++)
#pragma unroll
                for (int j = 0; j < 4; j++) acc[i][j] += a[i] * b[j];
        }
        __syncthreads();
    }

#pragma unroll
    for (int i = 0; i < 8; i++) {
        int r = row0 + i;
        float bi = bias[r];
        float4 v;
        v.x = acc[i][0] + bi; v.y = acc[i][1] + bi;
        v.z = acc[i][2] + bi; v.w = acc[i][3] + bi;
        if (EPI == 1) {
            v.x = fmaxf(v.x, 0.f); v.y = fmaxf(v.y, 0.f);
            v.z = fmaxf(v.z, 0.f); v.w = fmaxf(v.w, 0.f);
        }
        if (EPI == 2) {
            float4 rr = *(const float4*)&Rp[(size_t)r * N + col0];
            v.x += rr.x; v.y += rr.y; v.z += rr.z; v.w += rr.w;
        }
        *(float4*)&Cp[(size_t)r * N + col0] = v;
    }
}

// ---------------------------------------------------------------------------
// Flash attention, fp32. One block = 64 queries for one (batch, head).
// q/k/v in channel-major layout [b, c=h*32+d, p]. grid = (49, 8, 2), 256 thr.
// ---------------------------------------------------------------------------
__global__ void __launch_bounds__(256)
attn_kernel(const float* __restrict__ q, const float* __restrict__ k,
            const float* __restrict__ v, float* __restrict__ o) {
    const int qt = blockIdx.x;
    const int h  = blockIdx.y;
    const int b  = blockIdx.z;
    const size_t headoff = ((size_t)b * C + h * HD) * HW;
    const float* qp = q + headoff;
    const float* kp = k + headoff;
    const float* vp = v + headoff;
    float* op = o + headoff;

    __shared__ float Qs[32][64];
    __shared__ float Ks[32][64];
    __shared__ float Vs[64][34];
    __shared__ float Ps[64][68];

    const int tid = threadIdx.x;
    const int tx = tid & 15;
    const int ty = tid >> 4;
    const float scale = 0.17677669529663687f;   // 1/sqrt(32)

    // load Q tile (pre-scaled), d-major
    for (int i = tid; i < 2048; i += 256) {
        int d = i >> 6, p = i & 63;
        Qs[d][p] = qp[(size_t)d * HW + qt * 64 + p] * scale;
    }

    float m[4], l[4], acc[4][2];
#pragma unroll
    for (int r = 0; r < 4; r++) {
        m[r] = -INFINITY; l[r] = 0.f;
        acc[r][0] = 0.f; acc[r][1] = 0.f;
    }

    for (int kt = 0; kt < 49; kt++) {
        __syncthreads();   // previous PV done; also covers initial Q-store
        for (int i = tid; i < 2048; i += 256) {
            int d = i >> 6, p = i & 63;
            float kvv = kp[(size_t)d * HW + kt * 64 + p];
            float vvv = vp[(size_t)d * HW + kt * 64 + p];
            Ks[d][p] = kvv;
            Vs[p][d] = vvv;
        }
        __syncthreads();

        // S = Q K^T  (4x4 per thread)
        float s[4][4];
#pragma unroll
        for (int r = 0; r < 4; r++)
#pragma unroll
            for (int c = 0; c < 4; c++) s[r][c] = 0.f;
#pragma unroll
        for (int d = 0; d < 32; d++) {
            float a[4], bb[4];
            *(float4*)a  = *(const float4*)&Qs[d][ty * 4];
            *(float4*)bb = *(const float4*)&Ks[d][tx * 4];
#pragma unroll
            for (int r = 0; r < 4; r++)
#pragma unroll
                for (int c = 0; c < 4; c++) s[r][c] += a[r] * bb[c];
        }

        // online softmax per row (rows shared across the 16 tx lanes)
#pragma unroll
        for (int r = 0; r < 4; r++) {
            float tmax = fmaxf(fmaxf(s[r][0], s[r][1]), fmaxf(s[r][2], s[r][3]));
#pragma unroll
            for (int msk = 8; msk > 0; msk >>= 1)
                tmax = fmaxf(tmax, __shfl_xor_sync(0xffffffffu, tmax, msk, 16));
            float mnew = fmaxf(m[r], tmax);
            float alpha = __expf(m[r] - mnew);
            float rs = 0.f;
#pragma unroll
            for (int c = 0; c < 4; c++) {
                float p = __expf(s[r][c] - mnew);
                s[r][c] = p;
                rs += p;
            }
#pragma unroll
            for (int msk = 8; msk > 0; msk >>= 1)
                rs += __shfl_xor_sync(0xffffffffu, rs, msk, 16);
            l[r] = l[r] * alpha + rs;
            acc[r][0] *= alpha;
            acc[r][1] *= alpha;
            m[r] = mnew;
            *(float4*)&Ps[ty * 4 + r][tx * 4] =
                make_float4(s[r][0], s[r][1], s[r][2], s[r][3]);
        }
        __syncthreads();

        // O += P @ V  (4 rows x 2 dims per thread)
        const int d0 = tx * 2;
#pragma unroll
        for (int kk = 0; kk < 64; kk += 4) {
            float pr[4][4];
            float vv[4][2];
#pragma unroll
            for (int r = 0; r < 4; r++)
                *(float4*)pr[r] = *(const float4*)&Ps[ty * 4 + r][kk];
#pragma unroll
            for (int j = 0; j < 4; j++) {
                float2 t2 = *(const float2*)&Vs[kk + j][d0];
                vv[j][0] = t2.x; vv[j][1] = t2.y;
            }
#pragma unroll
            for (int r = 0; r < 4; r++)
#pragma unroll
                for (int j = 0; j < 4; j++) {
                    acc[r][0] += pr[r][j] * vv[j][0];
                    acc[r][1] += pr[r][j] * vv[j][1];
                }
        }
    }

    // normalize + write (channel-major)
    const int d0 = tx * 2;
#pragma unroll
    for (int r = 0; r < 4; r++) {
        float inv = 1.f / l[r];
        int p = qt * 64 + ty * 4 + r;
        op[(size_t)(d0 + 0) * HW + p] = acc[r][0] * inv;
        op[(size_t)(d0 + 1) * HW + p] = acc[r][1] * inv;
    }
}

// ---------------------------------------------------------------------------
// Launch
// ---------------------------------------------------------------------------
extern "C" void kernel_launch(void* const* d_in, const int* in_sizes, int n_in,
                              void* d_out, int out_size) {
    const float* x     = (const float*)d_in[0];
    const float* wq    = (const float*)d_in[1];
    const float* bq    = (const float*)d_in[2];
    const float* wk    = (const float*)d_in[3];
    const float* bk    = (const float*)d_in[4];
    const float* wv    = (const float*)d_in[5];
    const float* bv    = (const float*)d_in[6];
    const float* wo    = (const float*)d_in[7];
    const float* bo    = (const float*)d_in[8];
    const float* g1    = (const float*)d_in[9];
    const float* be1   = (const float*)d_in[10];
    const float* g2    = (const float*)d_in[11];
    const float* be2   = (const float*)d_in[12];
    const float* wm1   = (const float*)d_in[13];
    const float* bm1   = (const float*)d_in[14];
    const float* wm2   = (const float*)d_in[15];
    const float* bm2   = (const float*)d_in[16];
    float* out = (float*)d_out;

    float *s1, *t1, *s2, *t2, *wqf, *wkf, *wvf, *bqf, *bkf, *bvf;
    float *wm1f, *bm1f, *qb, *kb, *vb, *ao, *x2, *hb;
    cudaGetSymbolAddress((void**)&s1, g_s1);
    cudaGetSymbolAddress((void**)&t1, g_t1);
    cudaGetSymbolAddress((void**)&s2, g_s2);
    cudaGetSymbolAddress((void**)&t2, g_t2);
    cudaGetSymbolAddress((void**)&wqf, g_wq);
    cudaGetSymbolAddress((void**)&wkf, g_wk);
    cudaGetSymbolAddress((void**)&wvf, g_wv);
    cudaGetSymbolAddress((void**)&bqf, g_bq);
    cudaGetSymbolAddress((void**)&bkf, g_bk);
    cudaGetSymbolAddress((void**)&bvf, g_bv);
    cudaGetSymbolAddress((void**)&wm1f, g_wm1);
    cudaGetSymbolAddress((void**)&bm1f, g_bm1);
    cudaGetSymbolAddress((void**)&qb, g_q);
    cudaGetSymbolAddress((void**)&kb, g_k);
    cudaGetSymbolAddress((void**)&vb, g_v);
    cudaGetSymbolAddress((void**)&ao, g_ao);
    cudaGetSymbolAddress((void**)&x2, g_x2);
    cudaGetSymbolAddress((void**)&hb, g_h);

    // 1) BN1 stats + fold into QKV weights
    bn_stats_kernel<<<C, 256>>>(x, g1, be1, s1, t1);
    fold_kernel<<<C, 256>>>(wq, bq, s1, t1, wqf, bqf, C);
    fold_kernel<<<C, 256>>>(wk, bk, s1, t1, wkf, bkf, C);
    fold_kernel<<<C, 256>>>(wv, bv, s1, t1, wvf, bvf, C);

    // 2) QKV projections (channel-major outputs)
    dim3 ggrid(HW / 64, C / 128, BATCH);
    gemm_kernel<0><<<ggrid, 256>>>(wqf, x, bqf, nullptr, qb, C, C, HW);
    gemm_kernel<0><<<ggrid, 256>>>(wkf, x, bkf, nullptr, kb, C, C, HW);
    gemm_kernel<0><<<ggrid, 256>>>(wvf, x, bvf, nullptr, vb, C, C, HW);

    // 3) attention
    attn_kernel<<<dim3(HW / 64, HEADS, BATCH), 256>>>(qb, kb, vb, ao);

    // 4) output projection + residual -> x2
    gemm_kernel<2><<<ggrid, 256>>>(wo, ao, bo, x, x2, C, C, HW);

    // 5) BN2 stats + fold into MLP1 weights
    bn_stats_kernel<<<C, 256>>>(x2, g2, be2, s2, t2);
    fold_kernel<<<C4, 256>>>(wm1, bm1, s2, t2, wm1f, bm1f, C);

    // 6) MLP1 (+ReLU)
    gemm_kernel<1><<<dim3(HW / 64, C4 / 128, BATCH), 256>>>(wm1f, x2, bm1f, nullptr, hb, C4, C, HW);

    // 7) MLP2 + residual -> out
    gemm_kernel<2><<<ggrid, 256>>>(wm2, hb, bm2, x2, out, C, C4, HW);
}

// round 3
// speedup vs baseline: 1.1216x; 1.1216x over previous
#include <cuda_runtime.h>
#include <cuda_bf16.h>
#include <math.h>
#include <stdint.h>

// Problem constants
#define BATCH 2
#define C 256
#define HW 3136          // 56*56
#define HEADS 8
#define HD 32
#define EPS 1e-5f
#define C4 (4*C)         // 1024

// ---------------------------------------------------------------------------
// Scratch (device globals; no allocation allowed)
// ---------------------------------------------------------------------------
__device__ float g_s1[C], g_t1[C];          // BN1 folded scale/shift
__device__ float g_s2[C], g_t2[C];          // BN2 folded scale/shift
__device__ float g_wq[C*C], g_wk[C*C], g_wv[C*C];
__device__ float g_bq[C], g_bk[C], g_bv[C];
__device__ float g_wm1[C4*C];
__device__ float g_bm1[C4];
__device__ float g_q[BATCH*C*HW];
__device__ float g_k[BATCH*C*HW];
__device__ float g_v[BATCH*C*HW];
__device__ float g_ao[BATCH*C*HW];
__device__ float g_x2[BATCH*C*HW];
__device__ float g_h[BATCH*C4*HW];

// ---------------------------------------------------------------------------
// BN stats: per-channel mean/var over (B, HW); emit scale s = g*rsqrt(var+eps)
// and shift t = beta - mean*s
// ---------------------------------------------------------------------------
__global__ void bn_stats_kernel(const float* __restrict__ x,
                                const float* __restrict__ gamma,
                                const float* __restrict__ beta,
                                float* __restrict__ s, float* __restrict__ t) {
    int c = blockIdx.x;
    int tid = threadIdx.x;
    float sum = 0.f, sq = 0.f;
    for (int b = 0; b < BATCH; b++) {
        const float* p = x + ((size_t)b * C + c) * HW;
        for (int i = tid; i < HW; i += blockDim.x) {
            float v = p[i];
            sum += v; sq += v * v;
        }
    }
    __shared__ float rs[256], rq[256];
    rs[tid] = sum; rq[tid] = sq;
    __syncthreads();
    for (int off = 128; off > 0; off >>= 1) {
        if (tid < off) { rs[tid] += rs[tid + off]; rq[tid] += rq[tid + off]; }
        __syncthreads();
    }
    if (tid == 0) {
        const float n = (float)(BATCH * HW);
        float mean = rs[0] / n;
        float var  = rq[0] / n - mean * mean;
        float sc = gamma[c] * rsqrtf(var + EPS);
        s[c] = sc;
        t[c] = beta[c] - mean * sc;
    }
}

// ---------------------------------------------------------------------------
// Fold BN into conv weights: wf[o,c] = w[o,c]*s[c]; bf[o] = b[o] + sum_c w[o,c]*t[c]
// ---------------------------------------------------------------------------
__global__ void fold_kernel(const float* __restrict__ w, const float* __restrict__ bias,
                            const float* __restrict__ s, const float* __restrict__ t,
                            float* __restrict__ wf, float* __restrict__ bf, int K) {
    int o = blockIdx.x;
    int tid = threadIdx.x;
    float acc = 0.f;
    for (int c = tid; c < K; c += blockDim.x) {
        float wv = w[(size_t)o * K + c];
        wf[(size_t)o * K + c] = wv * s[c];
        acc += wv * t[c];
    }
    __shared__ float red[256];
    red[tid] = acc;
    __syncthreads();
    for (int off = 128; off > 0; off >>= 1) {
        if (tid < off) red[tid] += red[tid + off];
        __syncthreads();
    }
    if (tid == 0) bf[o] = bias[o] + red[0];
}

// ---------------------------------------------------------------------------
// tf32 helpers
// ---------------------------------------------------------------------------
__device__ __forceinline__ uint32_t f2tf(float x) {
    uint32_t y;
    asm("cvt.rna.tf32.f32 %0, %1;" : "=r"(y) : "f"(x));
    return y;
}

__device__ __forceinline__ void mma8(float* d, const float4 a, uint32_t b0, uint32_t b1) {
    asm volatile(
        "mma.sync.aligned.m16n8k8.row.col.f32.tf32.tf32.f32 "
        "{%0,%1,%2,%3}, {%4,%5,%6,%7}, {%8,%9}, {%0,%1,%2,%3};"
        : "+f"(d[0]), "+f"(d[1]), "+f"(d[2]), "+f"(d[3])
        : "r"(__float_as_uint(a.x)), "r"(__float_as_uint(a.y)),
          "r"(__float_as_uint(a.z)), "r"(__float_as_uint(a.w)),
          "r"(b0), "r"(b1));
}

// ---------------------------------------------------------------------------
// tf32 tensor-core GEMM: C[b] = A[M,K] * B[b][K,N] + bias (+epilogue)
// BM=128, BN=64, BK=32, 256 threads = 8 warps (4 warp_m x 2 warp_n).
// Warp tile 32x32 = mma grid 2(m) x 4(n), m16n8k8.
// Smem holds tiles in *fragment layout* (scatter at STS, LDS.128 at use).
// EPI: 0 = plain, 1 = relu, 2 = add residual
// grid = (N/64, M/128, BATCH)
// ---------------------------------------------------------------------------
template<int EPI>
__global__ void __launch_bounds__(256)
gemm_tc(const float* __restrict__ A, const float* __restrict__ Bm,
        const float* __restrict__ bias, const float* __restrict__ res,
        float* __restrict__ Cout, int M, int K, int N) {
    // A_s layout: [warp_m(4)][kstep(4)][mma_m(2)][lane(32)][4 regs]
    // B_s layout: [warp_n(2)][kstep(4)][pair(2)][lane(32)][4 regs]
    __shared__ float A_s[2][4096];
    __shared__ float B_s[2][2048];

    const int bn = blockIdx.x;
    const int bm = blockIdx.y;
    const int batch = blockIdx.z;
    const float* Bp = Bm + (size_t)batch * K * N;
    float* Cp = Cout + (size_t)batch * M * N;
    const float* Rp = (EPI == 2) ? (res + (size_t)batch * M * N) : nullptr;

    const int tid = threadIdx.x;
    const int lane = tid & 31;
    const int wid = tid >> 5;
    const int warp_m = wid & 3;
    const int warp_n = wid >> 2;

    float acc[2][4][4];
#pragma unroll
    for (int i = 0; i < 2; i++)
#pragma unroll
        for (int j = 0; j < 4; j++)
#pragma unroll
            for (int k = 0; k < 4; k++) acc[i][j][k] = 0.f;

    float4 aR[4];
    float4 bR[2];

    const int a_row[4] = { (0*256+tid) >> 3, (1*256+tid) >> 3, (2*256+tid) >> 3, (3*256+tid) >> 3 };
    const int a_kq [4] = { tid & 7, tid & 7, tid & 7, tid & 7 };
    const int b_kk [2] = { (0*256+tid) >> 4, (1*256+tid) >> 4 };
    const int b_nq [2] = { tid & 15, tid & 15 };

    const int iters = K >> 5;

#define LDG_TILE(K0)                                                              \
    do {                                                                          \
        _Pragma("unroll")                                                         \
        for (int i = 0; i < 4; i++)                                               \
            aR[i] = *(const float4*)&A[(size_t)(bm * 128 + a_row[i]) * K + (K0) + a_kq[i] * 4]; \
        _Pragma("unroll")                                                         \
        for (int i = 0; i < 2; i++)                                               \
            bR[i] = *(const float4*)&Bp[(size_t)((K0) + b_kk[i]) * N + bn * 64 + b_nq[i] * 4];  \
    } while (0)

#define STS_TILE(BUF)                                                             \
    do {                                                                          \
        _Pragma("unroll")                                                         \
        for (int i = 0; i < 4; i++) {                                             \
            float v4[4] = { aR[i].x, aR[i].y, aR[i].z, aR[i].w };                 \
            int row = a_row[i];                                                   \
            int wm = row >> 5, mr = row & 31, mm = mr >> 4, r = mr & 15;          \
            _Pragma("unroll")                                                     \
            for (int j = 0; j < 4; j++) {                                         \
                int lk = a_kq[i] * 4 + j;                                         \
                int ks = lk >> 3, c = lk & 7;                                     \
                int ln = ((r & 7) << 2) | (c & 3);                                \
                int rg = (r >> 3) | ((c >> 2) << 1);                              \
                A_s[BUF][((((wm * 4 + ks) * 2 + mm) * 32 + ln) << 2) + rg] =      \
                    __uint_as_float(f2tf(v4[j]));                                 \
            }                                                                     \
        }                                                                         \
        _Pragma("unroll")                                                         \
        for (int i = 0; i < 2; i++) {                                             \
            float v4[4] = { bR[i].x, bR[i].y, bR[i].z, bR[i].w };                 \
            int kk = b_kk[i];                                                     \
            int ks = kk >> 3, c = kk & 7;                                         \
            int rg = c >> 2;                                                      \
            _Pragma("unroll")                                                     \
            for (int j = 0; j < 4; j++) {                                         \
                int n = b_nq[i] * 4 + j;                                          \
                int wn = n >> 5, nn = n & 31, mn = nn >> 3, col = nn & 7;         \
                int ln = (col << 2) | (c & 3);                                    \
                B_s[BUF][((((wn * 4 + ks) * 2 + (mn >> 1)) * 32 + ln) << 2) +     \
                         ((mn & 1) << 1) + rg] = __uint_as_float(f2tf(v4[j]));    \
            }                                                                     \
        }                                                                         \
    } while (0)

    LDG_TILE(0);
    STS_TILE(0);
    __syncthreads();

    for (int it = 0; it < iters; ++it) {
        if (it + 1 < iters) LDG_TILE((it + 1) * 32);
        const int buf = it & 1;
#pragma unroll
        for (int ks = 0; ks < 4; ks++) {
            const float4* Ab =
                (const float4*)&A_s[buf][(((warp_m * 4 + ks) * 2 + 0) * 32 + lane) << 2];
            float4 a0 = Ab[0];
            float4 a1 = Ab[32];
            const float4* Bb =
                (const float4*)&B_s[buf][(((warp_n * 4 + ks) * 2 + 0) * 32 + lane) << 2];
            float4 b0 = Bb[0];
            float4 b1 = Bb[32];
            mma8(acc[0][0], a0, __float_as_uint(b0.x), __float_as_uint(b0.y));
            mma8(acc[0][1], a0, __float_as_uint(b0.z), __float_as_uint(b0.w));
            mma8(acc[0][2], a0, __float_as_uint(b1.x), __float_as_uint(b1.y));
            mma8(acc[0][3], a0, __float_as_uint(b1.z), __float_as_uint(b1.w));
            mma8(acc[1][0], a1, __float_as_uint(b0.x), __float_as_uint(b0.y));
            mma8(acc[1][1], a1, __float_as_uint(b0.z), __float_as_uint(b0.w));
            mma8(acc[1][2], a1, __float_as_uint(b1.x), __float_as_uint(b1.y));
            mma8(acc[1][3], a1, __float_as_uint(b1.z), __float_as_uint(b1.w));
        }
        if (it + 1 < iters) {
            STS_TILE((it + 1) & 1);
            __syncthreads();
        }
    }

    // Epilogue
#pragma unroll
    for (int mm = 0; mm < 2; mm++) {
        int r0 = bm * 128 + warp_m * 32 + mm * 16 + (lane >> 2);
        float bv0 = bias[r0];
        float bv1 = bias[r0 + 8];
#pragma unroll
        for (int mn = 0; mn < 4; mn++) {
            int col = bn * 64 + warp_n * 32 + mn * 8 + (lane & 3) * 2;
            float2 v0 = make_float2(acc[mm][mn][0] + bv0, acc[mm][mn][1] + bv0);
            float2 v1 = make_float2(acc[mm][mn][2] + bv1, acc[mm][mn][3] + bv1);
            if (EPI == 1) {
                v0.x = fmaxf(v0.x, 0.f); v0.y = fmaxf(v0.y, 0.f);
                v1.x = fmaxf(v1.x, 0.f); v1.y = fmaxf(v1.y, 0.f);
            }
            if (EPI == 2) {
                float2 r0v = *(const float2*)&Rp[(size_t)r0 * N + col];
                float2 r1v = *(const float2*)&Rp[(size_t)(r0 + 8) * N + col];
                v0.x += r0v.x; v0.y += r0v.y;
                v1.x += r1v.x; v1.y += r1v.y;
            }
            *(float2*)&Cp[(size_t)r0 * N + col] = v0;
            *(float2*)&Cp[(size_t)(r0 + 8) * N + col] = v1;
        }
    }
#undef LDG_TILE
#undef STS_TILE
}

// ---------------------------------------------------------------------------
// Flash attention, fp32. One block = 64 queries for one (batch, head).
// q/k/v in channel-major layout [b, c=h*32+d, p]. grid = (49, 8, 2), 256 thr.
// ---------------------------------------------------------------------------
__global__ void __launch_bounds__(256)
attn_kernel(const float* __restrict__ q, const float* __restrict__ k,
            const float* __restrict__ v, float* __restrict__ o) {
    const int qt = blockIdx.x;
    const int h  = blockIdx.y;
    const int b  = blockIdx.z;
    const size_t headoff = ((size_t)b * C + h * HD) * HW;
    const float* qp = q + headoff;
    const float* kp = k + headoff;
    const float* vp = v + headoff;
    float* op = o + headoff;

    __shared__ float Qs[32][64];
    __shared__ float Ks[32][64];
    __shared__ float Vs[64][34];
    __shared__ float Ps[64][68];

    const int tid = threadIdx.x;
    const int tx = tid & 15;
    const int ty = tid >> 4;
    const float scale = 0.17677669529663687f;   // 1/sqrt(32)

    for (int i = tid; i < 2048; i += 256) {
        int d = i >> 6, p = i & 63;
        Qs[d][p] = qp[(size_t)d * HW + qt * 64 + p] * scale;
    }

    float m[4], l[4], acc[4][2];
#pragma unroll
    for (int r = 0; r < 4; r++) {
        m[r] = -INFINITY; l[r] = 0.f;
        acc[r][0] = 0.f; acc[r][1] = 0.f;
    }

    for (int kt = 0; kt < 49; kt++) {
        __syncthreads();
        for (int i = tid; i < 2048; i += 256) {
            int d = i >> 6, p = i & 63;
            float kvv = kp[(size_t)d * HW + kt * 64 + p];
            float vvv = vp[(size_t)d * HW + kt * 64 + p];
            Ks[d][p] = kvv;
            Vs[p][d] = vvv;
        }
        __syncthreads();

        float s[4][4];
#pragma unroll
        for (int r = 0; r < 4; r++)
#pragma unroll
            for (int c = 0; c < 4; c++) s[r][c] = 0.f;
#pragma unroll
        for (int d = 0; d < 32; d++) {
            float a[4], bb[4];
            *(float4*)a  = *(const float4*)&Qs[d][ty * 4];
            *(float4*)bb = *(const float4*)&Ks[d][tx * 4];
#pragma unroll
            for (int r = 0; r < 4; r++)
#pragma unroll
                for (int c = 0; c < 4; c++) s[r][c] += a[r] * bb[c];
        }

#pragma unroll
        for (int r = 0; r < 4; r++) {
            float tmax = fmaxf(fmaxf(s[r][0], s[r][1]), fmaxf(s[r][2], s[r][3]));
#pragma unroll
            for (int msk = 8; msk > 0; msk >>= 1)
                tmax = fmaxf(tmax, __shfl_xor_sync(0xffffffffu, tmax, msk, 16));
            float mnew = fmaxf(m[r], tmax);
            float alpha = __expf(m[r] - mnew);
            float rs = 0.f;
#pragma unroll
            for (int c = 0; c < 4; c++) {
                float p = __expf(s[r][c] - mnew);
                s[r][c] = p;
                rs += p;
            }
#pragma unroll
            for (int msk = 8; msk > 0; msk >>= 1)
                rs += __shfl_xor_sync(0xffffffffu, rs, msk, 16);
            l[r] = l[r] * alpha + rs;
            acc[r][0] *= alpha;
            acc[r][1] *= alpha;
            m[r] = mnew;
            *(float4*)&Ps[ty * 4 + r][tx * 4] =
                make_float4(s[r][0], s[r][1], s[r][2], s[r][3]);
        }
        __syncthreads();

        const int d0 = tx * 2;
#pragma unroll
        for (int kk = 0; kk < 64; kk += 4) {
            float pr[4][4];
            float vv[4][2];
#pragma unroll
            for (int r = 0; r < 4; r++)
                *(float4*)pr[r] = *(const float4*)&Ps[ty * 4 + r][kk];
#pragma unroll
            for (int j = 0; j < 4; j++) {
                float2 t2 = *(const float2*)&Vs[kk + j][d0];
                vv[j][0] = t2.x; vv[j][1] = t2.y;
            }
#pragma unroll
            for (int r = 0; r < 4; r++)
#pragma unroll
                for (int j = 0; j < 4; j++) {
                    acc[r][0] += pr[r][j] * vv[j][0];
                    acc[r][1] += pr[r][j] * vv[j][1];
                }
        }
    }

    const int d0 = tx * 2;
#pragma unroll
    for (int r = 0; r < 4; r++) {
        float inv = 1.f / l[r];
        int p = qt * 64 + ty * 4 + r;
        op[(size_t)(d0 + 0) * HW + p] = acc[r][0] * inv;
        op[(size_t)(d0 + 1) * HW + p] = acc[r][1] * inv;
    }
}

// ---------------------------------------------------------------------------
// Launch
// ---------------------------------------------------------------------------
extern "C" void kernel_launch(void* const* d_in, const int* in_sizes, int n_in,
                              void* d_out, int out_size) {
    const float* x     = (const float*)d_in[0];
    const float* wq    = (const float*)d_in[1];
    const float* bq    = (const float*)d_in[2];
    const float* wk    = (const float*)d_in[3];
    const float* bk    = (const float*)d_in[4];
    const float* wv    = (const float*)d_in[5];
    const float* bv    = (const float*)d_in[6];
    const float* wo    = (const float*)d_in[7];
    const float* bo    = (const float*)d_in[8];
    const float* g1    = (const float*)d_in[9];
    const float* be1   = (const float*)d_in[10];
    const float* g2    = (const float*)d_in[11];
    const float* be2   = (const float*)d_in[12];
    const float* wm1   = (const float*)d_in[13];
    const float* bm1   = (const float*)d_in[14];
    const float* wm2   = (const float*)d_in[15];
    const float* bm2   = (const float*)d_in[16];
    float* out = (float*)d_out;

    float *s1, *t1, *s2, *t2, *wqf, *wkf, *wvf, *bqf, *bkf, *bvf;
    float *wm1f, *bm1f, *qb, *kb, *vb, *ao, *x2, *hb;
    cudaGetSymbolAddress((void**)&s1, g_s1);
    cudaGetSymbolAddress((void**)&t1, g_t1);
    cudaGetSymbolAddress((void**)&s2, g_s2);
    cudaGetSymbolAddress((void**)&t2, g_t2);
    cudaGetSymbolAddress((void**)&wqf, g_wq);
    cudaGetSymbolAddress((void**)&wkf, g_wk);
    cudaGetSymbolAddress((void**)&wvf, g_wv);
    cudaGetSymbolAddress((void**)&bqf, g_bq);
    cudaGetSymbolAddress((void**)&bkf, g_bk);
    cudaGetSymbolAddress((void**)&bvf, g_bv);
    cudaGetSymbolAddress((void**)&wm1f, g_wm1);
    cudaGetSymbolAddress((void**)&bm1f, g_bm1);
    cudaGetSymbolAddress((void**)&qb, g_q);
    cudaGetSymbolAddress((void**)&kb, g_k);
    cudaGetSymbolAddress((void**)&vb, g_v);
    cudaGetSymbolAddress((void**)&ao, g_ao);
    cudaGetSymbolAddress((void**)&x2, g_x2);
    cudaGetSymbolAddress((void**)&hb, g_h);

    // 1) BN1 stats + fold into QKV weights
    bn_stats_kernel<<<C, 256>>>(x, g1, be1, s1, t1);
    fold_kernel<<<C, 256>>>(wq, bq, s1, t1, wqf, bqf, C);
    fold_kernel<<<C, 256>>>(wk, bk, s1, t1, wkf, bkf, C);
    fold_kernel<<<C, 256>>>(wv, bv, s1, t1, wvf, bvf, C);

    // 2) QKV projections (channel-major outputs), tf32 tensor cores
    dim3 ggrid(HW / 64, C / 128, BATCH);
    gemm_tc<0><<<ggrid, 256>>>(wqf, x, bqf, nullptr, qb, C, C, HW);
    gemm_tc<0><<<ggrid, 256>>>(wkf, x, bkf, nullptr, kb, C, C, HW);
    gemm_tc<0><<<ggrid, 256>>>(wvf, x, bvf, nullptr, vb, C, C, HW);

    // 3) attention
    attn_kernel<<<dim3(HW / 64, HEADS, BATCH), 256>>>(qb, kb, vb, ao);

    // 4) output projection + residual -> x2
    gemm_tc<2><<<ggrid, 256>>>(wo, ao, bo, x, x2, C, C, HW);

    // 5) BN2 stats + fold into MLP1 weights
    bn_stats_kernel<<<C, 256>>>(x2, g2, be2, s2, t2);
    fold_kernel<<<C4, 256>>>(wm1, bm1, s2, t2, wm1f, bm1f, C);

    // 6) MLP1 (+ReLU)
    gemm_tc<1><<<dim3(HW / 64, C4 / 128, BATCH), 256>>>(wm1f, x2, bm1f, nullptr, hb, C4, C, HW);

    // 7) MLP2 + residual -> out
    gemm_tc<2><<<ggrid, 256>>>(wm2, hb, bm2, x2, out, C, C4, HW);
}

// round 6
// speedup vs baseline: 1.8224x; 1.6247x over previous
#include <cuda_runtime.h>
#include <cuda_bf16.h>
#include <math.h>
#include <stdint.h>

// Problem constants
#define BATCH 2
#define C 256
#define HW 3136          // 56*56
#define HEADS 8
#define HD 32
#define EPS 1e-5f
#define C4 (4*C)         // 1024

// ---------------------------------------------------------------------------
// Scratch (device globals; no allocation allowed)
// ---------------------------------------------------------------------------
__device__ float g_s1[C], g_t1[C];
__device__ float g_s2[C], g_t2[C];
__device__ float g_wqkv[3*C*C];
__device__ float g_bqkv[3*C];
__device__ float g_wm1[C4*C];
__device__ float g_bm1[C4];
__device__ float g_qkv[BATCH*3*C*HW];
__device__ float g_ao[BATCH*C*HW];
__device__ float g_x2[BATCH*C*HW];
__device__ float g_h[BATCH*C4*HW];

// ---------------------------------------------------------------------------
// BN stats
// ---------------------------------------------------------------------------
__global__ void bn_stats_kernel(const float* __restrict__ x,
                                const float* __restrict__ gamma,
                                const float* __restrict__ beta,
                                float* __restrict__ s, float* __restrict__ t) {
    int c = blockIdx.x;
    int tid = threadIdx.x;
    float sum = 0.f, sq = 0.f;
    for (int b = 0; b < BATCH; b++) {
        const float* p = x + ((size_t)b * C + c) * HW;
        for (int i = tid; i < HW; i += blockDim.x) {
            float v = p[i];
            sum += v; sq += v * v;
        }
    }
    __shared__ float rs[256], rq[256];
    rs[tid] = sum; rq[tid] = sq;
    __syncthreads();
    for (int off = 128; off > 0; off >>= 1) {
        if (tid < off) { rs[tid] += rs[tid + off]; rq[tid] += rq[tid + off]; }
        __syncthreads();
    }
    if (tid == 0) {
        const float n = (float)(BATCH * HW);
        float mean = rs[0] / n;
        float var  = rq[0] / n - mean * mean;
        float sc = gamma[c] * rsqrtf(var + EPS);
        s[c] = sc;
        t[c] = beta[c] - mean * sc;
    }
}

// ---------------------------------------------------------------------------
// Fold BN into conv weights
// ---------------------------------------------------------------------------
__global__ void fold_kernel(const float* __restrict__ w, const float* __restrict__ bias,
                            const float* __restrict__ s, const float* __restrict__ t,
                            float* __restrict__ wf, float* __restrict__ bf, int K) {
    int o = blockIdx.x;
    int tid = threadIdx.x;
    float acc = 0.f;
    for (int c = tid; c < K; c += blockDim.x) {
        float wv = w[(size_t)o * K + c];
        wf[(size_t)o * K + c] = wv * s[c];
        acc += wv * t[c];
    }
    __shared__ float red[256];
    red[tid] = acc;
    __syncthreads();
    for (int off = 128; off > 0; off >>= 1) {
        if (tid < off) red[tid] += red[tid + off];
        __syncthreads();
    }
    if (tid == 0) bf[o] = bias[o] + red[0];
}

// ---------------------------------------------------------------------------
// tf32 helpers
// ---------------------------------------------------------------------------
__device__ __forceinline__ uint32_t f2tf(float x) {
    uint32_t y;
    asm("cvt.rna.tf32.f32 %0, %1;" : "=r"(y) : "f"(x));
    return y;
}

__device__ __forceinline__ void mma8(float* d, const float4 a, uint32_t b0, uint32_t b1) {
    asm volatile(
        "mma.sync.aligned.m16n8k8.row.col.f32.tf32.tf32.f32 "
        "{%0,%1,%2,%3}, {%4,%5,%6,%7}, {%8,%9}, {%0,%1,%2,%3};"
        : "+f"(d[0]), "+f"(d[1]), "+f"(d[2]), "+f"(d[3])
        : "r"(__float_as_uint(a.x)), "r"(__float_as_uint(a.y)),
          "r"(__float_as_uint(a.z)), "r"(__float_as_uint(a.w)),
          "r"(b0), "r"(b1));
}

__device__ __forceinline__ void mma8r(float* d, uint32_t a0, uint32_t a1,
                                      uint32_t a2, uint32_t a3,
                                      uint32_t b0, uint32_t b1) {
    asm volatile(
        "mma.sync.aligned.m16n8k8.row.col.f32.tf32.tf32.f32 "
        "{%0,%1,%2,%3}, {%4,%5,%6,%7}, {%8,%9}, {%0,%1,%2,%3};"
        : "+f"(d[0]), "+f"(d[1]), "+f"(d[2]), "+f"(d[3])
        : "r"(a0), "r"(a1), "r"(a2), "r"(a3), "r"(b0), "r"(b1));
}

// ---------------------------------------------------------------------------
// tf32 tensor-core GEMM (unchanged from R3)
// ---------------------------------------------------------------------------
template<int EPI>
__global__ void __launch_bounds__(256)
gemm_tc(const float* __restrict__ A, const float* __restrict__ Bm,
        const float* __restrict__ bias, const float* __restrict__ res,
        float* __restrict__ Cout, int M, int K, int N) {
    __shared__ float A_s[2][4096];
    __shared__ float B_s[2][2048];

    const int bn = blockIdx.x;
    const int bm = blockIdx.y;
    const int batch = blockIdx.z;
    const float* Bp = Bm + (size_t)batch * K * N;
    float* Cp = Cout + (size_t)batch * M * N;
    const float* Rp = (EPI == 2) ? (res + (size_t)batch * M * N) : nullptr;

    const int tid = threadIdx.x;
    const int lane = tid & 31;
    const int wid = tid >> 5;
    const int warp_m = wid & 3;
    const int warp_n = wid >> 2;

    float acc[2][4][4];
#pragma unroll
    for (int i = 0; i < 2; i++)
#pragma unroll
        for (int j = 0; j < 4; j++)
#pragma unroll
            for (int k = 0; k < 4; k++) acc[i][j][k] = 0.f;

    float4 aR[4];
    float4 bR[2];

    const int a_row[4] = { (0*256+tid) >> 3, (1*256+tid) >> 3, (2*256+tid) >> 3, (3*256+tid) >> 3 };
    const int a_kq [4] = { tid & 7, tid & 7, tid & 7, tid & 7 };
    const int b_kk [2] = { (0*256+tid) >> 4, (1*256+tid) >> 4 };
    const int b_nq [2] = { tid & 15, tid & 15 };

    const int iters = K >> 5;

#define LDG_TILE(K0)                                                              \
    do {                                                                          \
        _Pragma("unroll")                                                         \
        for (int i = 0; i < 4; i++)                                               \
            aR[i] = *(const float4*)&A[(size_t)(bm * 128 + a_row[i]) * K + (K0) + a_kq[i] * 4]; \
        _Pragma("unroll")                                                         \
        for (int i = 0; i < 2; i++)                                               \
            bR[i] = *(const float4*)&Bp[(size_t)((K0) + b_kk[i]) * N + bn * 64 + b_nq[i] * 4];  \
    } while (0)

#define STS_TILE(BUF)                                                             \
    do {                                                                          \
        _Pragma("unroll")                                                         \
        for (int i = 0; i < 4; i++) {                                             \
            float v4[4] = { aR[i].x, aR[i].y, aR[i].z, aR[i].w };                 \
            int row = a_row[i];                                                   \
            int wm = row >> 5, mr = row & 31, mm = mr >> 4, r = mr & 15;          \
            _Pragma("unroll")                                                     \
            for (int j = 0; j < 4; j++) {                                         \
                int lk = a_kq[i] * 4 + j;                                         \
                int ks = lk >> 3, c = lk & 7;                                     \
                int ln = ((r & 7) << 2) | (c & 3);                                \
                int rg = (r >> 3) | ((c >> 2) << 1);                              \
                A_s[BUF][((((wm * 4 + ks) * 2 + mm) * 32 + ln) << 2) + rg] =      \
                    __uint_as_float(f2tf(v4[j]));                                 \
            }                                                                     \
        }                                                                         \
        _Pragma("unroll")                                                         \
        for (int i = 0; i < 2; i++) {                                             \
            float v4[4] = { bR[i].x, bR[i].y, bR[i].z, bR[i].w };                 \
            int kk = b_kk[i];                                                     \
            int ks = kk >> 3, c = kk & 7;                                         \
            int rg = c >> 2;                                                      \
            _Pragma("unroll")                                                     \
            for (int j = 0; j < 4; j++) {                                         \
                int n = b_nq[i] * 4 + j;                                          \
                int wn = n >> 5, nn = n & 31, mn = nn >> 3, col = nn & 7;         \
                int ln = (col << 2) | (c & 3);                                    \
                B_s[BUF][((((wn * 4 + ks) * 2 + (mn >> 1)) * 32 + ln) << 2) +     \
                         ((mn & 1) << 1) + rg] = __uint_as_float(f2tf(v4[j]));    \
            }                                                                     \
        }                                                                         \
    } while (0)

    LDG_TILE(0);
    STS_TILE(0);
    __syncthreads();

    for (int it = 0; it < iters; ++it) {
        if (it + 1 < iters) LDG_TILE((it + 1) * 32);
        const int buf = it & 1;
#pragma unroll
        for (int ks = 0; ks < 4; ks++) {
            const float4* Ab =
                (const float4*)&A_s[buf][(((warp_m * 4 + ks) * 2 + 0) * 32 + lane) << 2];
            float4 a0 = Ab[0];
            float4 a1 = Ab[32];
            const float4* Bb =
                (const float4*)&B_s[buf][(((warp_n * 4 + ks) * 2 + 0) * 32 + lane) << 2];
            float4 b0 = Bb[0];
            float4 b1 = Bb[32];
            mma8(acc[0][0], a0, __float_as_uint(b0.x), __float_as_uint(b0.y));
            mma8(acc[0][1], a0, __float_as_uint(b0.z), __float_as_uint(b0.w));
            mma8(acc[0][2], a0, __float_as_uint(b1.x), __float_as_uint(b1.y));
            mma8(acc[0][3], a0, __float_as_uint(b1.z), __float_as_uint(b1.w));
            mma8(acc[1][0], a1, __float_as_uint(b0.x), __float_as_uint(b0.y));
            mma8(acc[1][1], a1, __float_as_uint(b0.z), __float_as_uint(b0.w));
            mma8(acc[1][2], a1, __float_as_uint(b1.x), __float_as_uint(b1.y));
            mma8(acc[1][3], a1, __float_as_uint(b1.z), __float_as_uint(b1.w));
        }
        if (it + 1 < iters) {
            STS_TILE((it + 1) & 1);
            __syncthreads();
        }
    }

#pragma unroll
    for (int mm = 0; mm < 2; mm++) {
        int r0 = bm * 128 + warp_m * 32 + mm * 16 + (lane >> 2);
        float bv0 = bias[r0];
        float bv1 = bias[r0 + 8];
#pragma unroll
        for (int mn = 0; mn < 4; mn++) {
            int col = bn * 64 + warp_n * 32 + mn * 8 + (lane & 3) * 2;
            float2 v0 = make_float2(acc[mm][mn][0] + bv0, acc[mm][mn][1] + bv0);
            float2 v1 = make_float2(acc[mm][mn][2] + bv1, acc[mm][mn][3] + bv1);
            if (EPI == 1) {
                v0.x = fmaxf(v0.x, 0.f); v0.y = fmaxf(v0.y, 0.f);
                v1.x = fmaxf(v1.x, 0.f); v1.y = fmaxf(v1.y, 0.f);
            }
            if (EPI == 2) {
                float2 r0v = *(const float2*)&Rp[(size_t)r0 * N + col];
                float2 r1v = *(const float2*)&Rp[(size_t)(r0 + 8) * N + col];
                v0.x += r0v.x; v0.y += r0v.y;
                v1.x += r1v.x; v1.y += r1v.y;
            }
            *(float2*)&Cp[(size_t)r0 * N + col] = v0;
            *(float2*)&Cp[(size_t)(r0 + 8) * N + col] = v1;
        }
    }
#undef LDG_TILE
#undef STS_TILE
}

// ---------------------------------------------------------------------------
// Tensor-core flash attention (tf32 m16n8k8).
// Block = 64 queries, 128 threads = 4 warps; warp w owns query rows w*16..+15.
// qkv layout: [b][3*C][HW] (q: rows 0..255, k: 256..511, v: 512..767).
// grid = (49, 8, 2).
// ---------------------------------------------------------------------------
__global__ void __launch_bounds__(128)
attn_tc(const float* __restrict__ qkv, float* __restrict__ o) {
    const int qt = blockIdx.x;
    const int h  = blockIdx.y;
    const int b  = blockIdx.z;
    const float* qp = qkv + ((size_t)b * 3 * C + h * HD) * HW;
    const float* kp = qp + (size_t)C * HW;
    const float* vp = qp + (size_t)2 * C * HW;
    float* op = o + ((size_t)b * C + h * HD) * HW;

    __shared__ float Qs[64][36];   // [q][d]   A-frag reads conflict-free
    __shared__ float Ks[64][36];   // [p][d]   B-frag reads conflict-free
    __shared__ float Vs[64][40];   // [p][d]   B-frag reads conflict-free
    __shared__ float Ps[64][68];   // [q][p]   P staging (64 cols!) / O staging

    const int tid  = threadIdx.x;
    const int lane = tid & 31;
    const int warp = tid >> 5;
    const int g    = lane >> 2;     // group id 0..7
    const int t4   = lane & 3;      // thread-in-group 0..3
    const int q0   = qt * 64;
    const int r0   = warp * 16 + g; // fragment row 0 (local)
    const int r1   = r0 + 8;        // fragment row 1 (local)
    const float scale = 0.17677669529663687f;

    // Q tile: pre-scale + tf32-round
    for (int i = tid; i < 2048; i += 128) {
        int d = i >> 6, p = i & 63;
        Qs[p][d] = __uint_as_float(f2tf(qp[(size_t)d * HW + q0 + p] * scale));
    }

    float m0 = -INFINITY, m1 = -INFINITY, l0 = 0.f, l1 = 0.f;
    float oacc[4][4];
#pragma unroll
    for (int i = 0; i < 4; i++)
#pragma unroll
        for (int j = 0; j < 4; j++) oacc[i][j] = 0.f;

    for (int kt = 0; kt < 49; kt++) {
        __syncthreads();
        for (int i = tid; i < 2048; i += 128) {
            int d = i >> 6, p = i & 63;
            size_t gidx = (size_t)d * HW + kt * 64 + p;
            Ks[p][d] = __uint_as_float(f2tf(kp[gidx]));
            Vs[p][d] = __uint_as_float(f2tf(vp[gidx]));
        }
        __syncthreads();

        // ---- S = Q K^T : 8 n-tiles x 4 k-steps per warp ----
        float s[8][4];
#pragma unroll
        for (int nt = 0; nt < 8; nt++)
#pragma unroll
            for (int j = 0; j < 4; j++) s[nt][j] = 0.f;

#pragma unroll
        for (int ks = 0; ks < 4; ks++) {
            uint32_t a0 = __float_as_uint(Qs[r0][ks * 8 + t4]);
            uint32_t a1 = __float_as_uint(Qs[r1][ks * 8 + t4]);
            uint32_t a2 = __float_as_uint(Qs[r0][ks * 8 + t4 + 4]);
            uint32_t a3 = __float_as_uint(Qs[r1][ks * 8 + t4 + 4]);
#pragma unroll
            for (int nt = 0; nt < 8; nt++) {
                uint32_t b0 = __float_as_uint(Ks[nt * 8 + g][ks * 8 + t4]);
                uint32_t b1 = __float_as_uint(Ks[nt * 8 + g][ks * 8 + t4 + 4]);
                mma8r(s[nt], a0, a1, a2, a3, b0, b1);
            }
        }

        // ---- online softmax on C-fragments ----
        float mx0 = -INFINITY, mx1 = -INFINITY;
#pragma unroll
        for (int nt = 0; nt < 8; nt++) {
            mx0 = fmaxf(mx0, fmaxf(s[nt][0], s[nt][1]));
            mx1 = fmaxf(mx1, fmaxf(s[nt][2], s[nt][3]));
        }
        mx0 = fmaxf(mx0, __shfl_xor_sync(0xffffffffu, mx0, 1));
        mx0 = fmaxf(mx0, __shfl_xor_sync(0xffffffffu, mx0, 2));
        mx1 = fmaxf(mx1, __shfl_xor_sync(0xffffffffu, mx1, 1));
        mx1 = fmaxf(mx1, __shfl_xor_sync(0xffffffffu, mx1, 2));

        float mn0 = fmaxf(m0, mx0);
        float mn1 = fmaxf(m1, mx1);
        float al0 = __expf(m0 - mn0);
        float al1 = __expf(m1 - mn1);
        m0 = mn0; m1 = mn1;

        float rs0 = 0.f, rs1 = 0.f;
#pragma unroll
        for (int nt = 0; nt < 8; nt++) {
            float p00 = __expf(s[nt][0] - mn0);
            float p01 = __expf(s[nt][1] - mn0);
            float p10 = __expf(s[nt][2] - mn1);
            float p11 = __expf(s[nt][3] - mn1);
            rs0 += p00 + p01;
            rs1 += p10 + p11;
            int c0 = nt * 8 + 2 * t4;
            Ps[r0][c0]     = __uint_as_float(f2tf(p00));
            Ps[r0][c0 + 1] = __uint_as_float(f2tf(p01));
            Ps[r1][c0]     = __uint_as_float(f2tf(p10));
            Ps[r1][c0 + 1] = __uint_as_float(f2tf(p11));
        }
        rs0 += __shfl_xor_sync(0xffffffffu, rs0, 1);
        rs0 += __shfl_xor_sync(0xffffffffu, rs0, 2);
        rs1 += __shfl_xor_sync(0xffffffffu, rs1, 1);
        rs1 += __shfl_xor_sync(0xffffffffu, rs1, 2);
        l0 = l0 * al0 + rs0;
        l1 = l1 * al1 + rs1;
#pragma unroll
        for (int nt = 0; nt < 4; nt++) {
            oacc[nt][0] *= al0; oacc[nt][1] *= al0;
            oacc[nt][2] *= al1; oacc[nt][3] *= al1;
        }
        __syncwarp();   // Ps rows are warp-private; order write->read

        // ---- O += P V : 8 k-steps x 4 n-tiles per warp ----
#pragma unroll
        for (int ks = 0; ks < 8; ks++) {
            uint32_t a0 = __float_as_uint(Ps[r0][ks * 8 + t4]);
            uint32_t a1 = __float_as_uint(Ps[r1][ks * 8 + t4]);
            uint32_t a2 = __float_as_uint(Ps[r0][ks * 8 + t4 + 4]);
            uint32_t a3 = __float_as_uint(Ps[r1][ks * 8 + t4 + 4]);
#pragma unroll
            for (int nt = 0; nt < 4; nt++) {
                uint32_t b0 = __float_as_uint(Vs[ks * 8 + t4][nt * 8 + g]);
                uint32_t b1 = __float_as_uint(Vs[ks * 8 + t4 + 4][nt * 8 + g]);
                mma8r(oacc[nt], a0, a1, a2, a3, b0, b1);
            }
        }
    }

    // ---- normalize + stage to smem (reuse Ps as Os[q][d]) + coalesced store
    __syncthreads();
    float inv0 = 1.f / l0;
    float inv1 = 1.f / l1;
#pragma unroll
    for (int nt = 0; nt < 4; nt++) {
        int c0 = nt * 8 + 2 * t4;
        Ps[r0][c0]     = oacc[nt][0] * inv0;
        Ps[r0][c0 + 1] = oacc[nt][1] * inv0;
        Ps[r1][c0]     = oacc[nt][2] * inv1;
        Ps[r1][c0 + 1] = oacc[nt][3] * inv1;
    }
    __syncthreads();
    for (int i = tid; i < 2048; i += 128) {
        int d = i >> 6, p = i & 63;
        op[(size_t)d * HW + q0 + p] = Ps[p][d];
    }
}

// ---------------------------------------------------------------------------
// Launch
// ---------------------------------------------------------------------------
extern "C" void kernel_launch(void* const* d_in, const int* in_sizes, int n_in,
                              void* d_out, int out_size) {
    const float* x     = (const float*)d_in[0];
    const float* wq    = (const float*)d_in[1];
    const float* bq    = (const float*)d_in[2];
    const float* wk    = (const float*)d_in[3];
    const float* bk    = (const float*)d_in[4];
    const float* wv    = (const float*)d_in[5];
    const float* bv    = (const float*)d_in[6];
    const float* wo    = (const float*)d_in[7];
    const float* bo    = (const float*)d_in[8];
    const float* g1    = (const float*)d_in[9];
    const float* be1   = (const float*)d_in[10];
    const float* g2    = (const float*)d_in[11];
    const float* be2   = (const float*)d_in[12];
    const float* wm1   = (const float*)d_in[13];
    const float* bm1   = (const float*)d_in[14];
    const float* wm2   = (const float*)d_in[15];
    const float* bm2   = (const float*)d_in[16];
    float* out = (float*)d_out;

    float *s1, *t1, *s2, *t2, *wqkvf, *bqkvf;
    float *wm1f, *bm1f, *qkvb, *ao, *x2, *hb;
    cudaGetSymbolAddress((void**)&s1, g_s1);
    cudaGetSymbolAddress((void**)&t1, g_t1);
    cudaGetSymbolAddress((void**)&s2, g_s2);
    cudaGetSymbolAddress((void**)&t2, g_t2);
    cudaGetSymbolAddress((void**)&wqkvf, g_wqkv);
    cudaGetSymbolAddress((void**)&bqkvf, g_bqkv);
    cudaGetSymbolAddress((void**)&wm1f, g_wm1);
    cudaGetSymbolAddress((void**)&bm1f, g_bm1);
    cudaGetSymbolAddress((void**)&qkvb, g_qkv);
    cudaGetSymbolAddress((void**)&ao, g_ao);
    cudaGetSymbolAddress((void**)&x2, g_x2);
    cudaGetSymbolAddress((void**)&hb, g_h);

    // 1) BN1 stats + fold into stacked QKV weights
    bn_stats_kernel<<<C, 256>>>(x, g1, be1, s1, t1);
    fold_kernel<<<C, 256>>>(wq, bq, s1, t1, wqkvf,           bqkvf,         C);
    fold_kernel<<<C, 256>>>(wk, bk, s1, t1, wqkvf + C * C,   bqkvf + C,     C);
    fold_kernel<<<C, 256>>>(wv, bv, s1, t1, wqkvf + 2*C*C,   bqkvf + 2*C,   C);

    // 2) fused QKV projection: M=768
    gemm_tc<0><<<dim3(HW / 64, 3 * C / 128, BATCH), 256>>>(wqkvf, x, bqkvf, nullptr, qkvb, 3 * C, C, HW);

    // 3) tensor-core flash attention
    attn_tc<<<dim3(HW / 64, HEADS, BATCH), 128>>>(qkvb, ao);

    // 4) output projection + residual -> x2
    dim3 ggrid(HW / 64, C / 128, BATCH);
    gemm_tc<2><<<ggrid, 256>>>(wo, ao, bo, x, x2, C, C, HW);

    // 5) BN2 stats + fold into MLP1 weights
    bn_stats_kernel<<<C, 256>>>(x2, g2, be2, s2, t2);
    fold_kernel<<<C4, 256>>>(wm1, bm1, s2, t2, wm1f, bm1f, C);

    // 6) MLP1 (+ReLU)
    gemm_tc<1><<<dim3(HW / 64, C4 / 128, BATCH), 256>>>(wm1f, x2, bm1f, nullptr, hb, C4, C, HW);

    // 7) MLP2 + residual -> out
    gemm_tc<2><<<ggrid, 256>>>(wm2, hb, bm2, x2, out, C, C4, HW);
}

// round 7
// speedup vs baseline: 4.0000x; 2.1950x over previous
#include <cuda_runtime.h>
#include <cuda_bf16.h>
#include <math.h>
#include <stdint.h>

// Problem constants
#define BATCH 2
#define C 256
#define HW 3136          // 56*56
#define HEADS 8
#define HD 32
#define EPS 1e-5f
#define C4 (4*C)         // 1024

// ---------------------------------------------------------------------------
// Scratch (device globals; no allocation allowed)
// ---------------------------------------------------------------------------
__device__ float    g_s1[C], g_t1[C];
__device__ float    g_s2[C], g_t2[C];
__device__ uint32_t g_wqkv_t[128*768];   // bf16x2 pairs along K, [k2][M]
__device__ float    g_bqkv[768];
__device__ uint32_t g_wo_t[128*256];
__device__ uint32_t g_wm1_t[128*1024];
__device__ float    g_bm1[1024];
__device__ uint32_t g_wm2_t[512*256];
__device__ float    g_qkv[BATCH*3*C*HW];
__device__ float    g_ao[BATCH*C*HW];
__device__ float    g_x2[BATCH*C*HW];
__device__ float    g_h[BATCH*C4*HW];

// ---------------------------------------------------------------------------
// bf16 helpers
// ---------------------------------------------------------------------------
__device__ __forceinline__ uint32_t pk(float lo, float hi) {
    uint32_t r;
    asm("cvt.rn.bf16x2.f32 %0, %1, %2;" : "=r"(r) : "f"(hi), "f"(lo));
    return r;
}

__device__ __forceinline__ void mma16(float* d, uint32_t a0, uint32_t a1,
                                      uint32_t a2, uint32_t a3,
                                      uint32_t b0, uint32_t b1) {
    asm volatile(
        "mma.sync.aligned.m16n8k16.row.col.f32.bf16.bf16.f32 "
        "{%0,%1,%2,%3}, {%4,%5,%6,%7}, {%8,%9}, {%0,%1,%2,%3};"
        : "+f"(d[0]), "+f"(d[1]), "+f"(d[2]), "+f"(d[3])
        : "r"(a0), "r"(a1), "r"(a2), "r"(a3), "r"(b0), "r"(b1));
}

// ---------------------------------------------------------------------------
// BN stats: s = gamma*rsqrt(var+eps), t = beta - mean*s
// ---------------------------------------------------------------------------
__global__ void bn_stats_kernel(const float* __restrict__ x,
                                const float* __restrict__ gamma,
                                const float* __restrict__ beta,
                                float* __restrict__ s, float* __restrict__ t) {
    int c = blockIdx.x;
    int tid = threadIdx.x;
    float sum = 0.f, sq = 0.f;
    for (int b = 0; b < BATCH; b++) {
        const float* p = x + ((size_t)b * C + c) * HW;
        for (int i = tid; i < HW; i += blockDim.x) {
            float v = p[i];
            sum += v; sq += v * v;
        }
    }
    __shared__ float rs[256], rq[256];
    rs[tid] = sum; rq[tid] = sq;
    __syncthreads();
    for (int off = 128; off > 0; off >>= 1) {
        if (tid < off) { rs[tid] += rs[tid + off]; rq[tid] += rq[tid + off]; }
        __syncthreads();
    }
    if (tid == 0) {
        const float n = (float)(BATCH * HW);
        float mean = rs[0] / n;
        float var  = rq[0] / n - mean * mean;
        float sc = gamma[c] * rsqrtf(var + EPS);
        s[c] = sc;
        t[c] = beta[c] - mean * sc;
    }
}

// ---------------------------------------------------------------------------
// Fold BN into conv weight; emit transposed bf16x2 pairs [k2][Mtot] + bias.
// K fixed = 256. grid = M blocks, 128 threads (one pair each).
// ---------------------------------------------------------------------------
__global__ void fold_bf(const float* __restrict__ w, const float* __restrict__ bias,
                        const float* __restrict__ s, const float* __restrict__ t,
                        uint32_t* __restrict__ wt, float* __restrict__ bf,
                        int Mtot, int off) {
    int o = blockIdx.x;
    int p = threadIdx.x;                      // pair index 0..127
    float w0 = w[(size_t)o * 256 + 2 * p];
    float w1 = w[(size_t)o * 256 + 2 * p + 1];
    float acc = w0 * t[2 * p] + w1 * t[2 * p + 1];
    wt[(size_t)p * Mtot + off + o] = pk(w0 * s[2 * p], w1 * s[2 * p + 1]);
    __shared__ float red[128];
    red[p] = acc;
    __syncthreads();
    for (int o2 = 64; o2 > 0; o2 >>= 1) {
        if (p < o2) red[p] += red[p + o2];
        __syncthreads();
    }
    if (p == 0) bf[off + o] = bias[o] + red[0];
}

// ---------------------------------------------------------------------------
// Pack weight (no fold): wt[p][o] = bf16x2(w[o][2p], w[o][2p+1]).
// grid = K/2 blocks, 256 threads over M.
// ---------------------------------------------------------------------------
__global__ void conv_w(const float* __restrict__ w, uint32_t* __restrict__ wt,
                       int K, int M) {
    int p = blockIdx.x;
    for (int o = threadIdx.x; o < M; o += blockDim.x)
        wt[(size_t)p * M + o] = pk(w[(size_t)o * K + 2 * p],
                                   w[(size_t)o * K + 2 * p + 1]);
}

// ---------------------------------------------------------------------------
// bf16 tensor-core GEMM: C[b] = Wt^T-logical A[M,K] * B[b][K,N] + bias (+epi)
// Wt: bf16x2 pairs along K, layout [K/2][M]. BM=128, BN=64, BK=32,
// 256 threads = 8 warps (4 warp_m x 2 warp_n), warp tile 32x32, m16n8k16.
// EPI: 0 plain, 1 relu, 2 +residual.  grid = (N/64, M/128, BATCH)
// ---------------------------------------------------------------------------
template<int EPI>
__global__ void __launch_bounds__(256)
gemm_bf(const uint32_t* __restrict__ Wt, const float* __restrict__ Bm,
        const float* __restrict__ bias, const float* __restrict__ res,
        float* __restrict__ Cout, int M, int K, int N) {
    __shared__ uint32_t As[2][16][136];   // [k2 local][m], pitch%32==8
    __shared__ uint32_t Bs[2][16][72];    // [k2 local][n], pitch%32==8

    const int bn = blockIdx.x;
    const int bm = blockIdx.y;
    const int batch = blockIdx.z;
    const float* Bp = Bm + (size_t)batch * K * N;
    float* Cp = Cout + (size_t)batch * M * N;
    const float* Rp = (EPI == 2) ? (res + (size_t)batch * M * N) : nullptr;

    const int tid = threadIdx.x;
    const int lane = tid & 31;
    const int wid = tid >> 5;
    const int warp_m = wid & 3;
    const int warp_n = wid >> 2;
    const int g = lane >> 2;
    const int t4 = lane & 3;

    float acc[2][4][4];
#pragma unroll
    for (int i = 0; i < 2; i++)
#pragma unroll
        for (int j = 0; j < 4; j++)
#pragma unroll
            for (int k = 0; k < 4; k++) acc[i][j][k] = 0.f;

    const int a_k2 = tid >> 5;            // 0..7
    const int a_m  = (tid & 31) * 4;
    const int b_k2 = tid >> 4;            // 0..15
    const int b_n  = (tid & 15) * 4;

    uint4 aR0, aR1;
    float4 bR0, bR1;

#define LDG_T(K2B)                                                             \
    do {                                                                       \
        aR0 = *(const uint4*)&Wt[(size_t)((K2B) + a_k2) * M + bm * 128 + a_m]; \
        aR1 = *(const uint4*)&Wt[(size_t)((K2B) + a_k2 + 8) * M + bm * 128 + a_m]; \
        const float* bp = &Bp[(size_t)(2 * (K2B) + 2 * b_k2) * N + bn * 64 + b_n]; \
        bR0 = *(const float4*)bp;                                              \
        bR1 = *(const float4*)(bp + N);                                        \
    } while (0)

#define STS_T(BUF)                                                             \
    do {                                                                       \
        *(uint4*)&As[BUF][a_k2][a_m] = aR0;                                    \
        *(uint4*)&As[BUF][a_k2 + 8][a_m] = aR1;                                \
        uint4 bb;                                                              \
        bb.x = pk(bR0.x, bR1.x); bb.y = pk(bR0.y, bR1.y);                      \
        bb.z = pk(bR0.z, bR1.z); bb.w = pk(bR0.w, bR1.w);                      \
        *(uint4*)&Bs[BUF][b_k2][b_n] = bb;                                     \
    } while (0)

    const int iters = K >> 5;
    LDG_T(0);
    STS_T(0);
    __syncthreads();

    for (int it = 0; it < iters; ++it) {
        if (it + 1 < iters) LDG_T((it + 1) * 16);
        const int buf = it & 1;
#pragma unroll
        for (int ks = 0; ks < 2; ks++) {
            uint32_t a[2][4];
#pragma unroll
            for (int mm = 0; mm < 2; mm++) {
                int r = warp_m * 32 + mm * 16 + g;
                a[mm][0] = As[buf][ks * 8 + t4][r];
                a[mm][1] = As[buf][ks * 8 + t4][r + 8];
                a[mm][2] = As[buf][ks * 8 + t4 + 4][r];
                a[mm][3] = As[buf][ks * 8 + t4 + 4][r + 8];
            }
#pragma unroll
            for (int nt = 0; nt < 4; nt++) {
                int n = warp_n * 32 + nt * 8 + g;
                uint32_t b0 = Bs[buf][ks * 8 + t4][n];
                uint32_t b1 = Bs[buf][ks * 8 + t4 + 4][n];
                mma16(acc[0][nt], a[0][0], a[0][1], a[0][2], a[0][3], b0, b1);
                mma16(acc[1][nt], a[1][0], a[1][1], a[1][2], a[1][3], b0, b1);
            }
        }
        if (it + 1 < iters) {
            STS_T((it + 1) & 1);
            __syncthreads();
        }
    }

    // Epilogue (C frag: c0,c1 at (g, 2*t4..+1); c2,c3 at (g+8, ...))
#pragma unroll
    for (int mm = 0; mm < 2; mm++) {
        int r0 = bm * 128 + warp_m * 32 + mm * 16 + g;
        float bv0 = bias[r0];
        float bv1 = bias[r0 + 8];
#pragma unroll
        for (int nt = 0; nt < 4; nt++) {
            int col = bn * 64 + warp_n * 32 + nt * 8 + t4 * 2;
            float2 v0 = make_float2(acc[mm][nt][0] + bv0, acc[mm][nt][1] + bv0);
            float2 v1 = make_float2(acc[mm][nt][2] + bv1, acc[mm][nt][3] + bv1);
            if (EPI == 1) {
                v0.x = fmaxf(v0.x, 0.f); v0.y = fmaxf(v0.y, 0.f);
                v1.x = fmaxf(v1.x, 0.f); v1.y = fmaxf(v1.y, 0.f);
            }
            if (EPI == 2) {
                float2 r0v = *(const float2*)&Rp[(size_t)r0 * N + col];
                float2 r1v = *(const float2*)&Rp[(size_t)(r0 + 8) * N + col];
                v0.x += r0v.x; v0.y += r0v.y;
                v1.x += r1v.x; v1.y += r1v.y;
            }
            *(float2*)&Cp[(size_t)r0 * N + col] = v0;
            *(float2*)&Cp[(size_t)(r0 + 8) * N + col] = v1;
        }
    }
#undef LDG_T
#undef STS_T
}

// ---------------------------------------------------------------------------
// bf16 tensor-core flash attention (m16n8k16).
// Block = 64 queries, 128 threads = 4 warps; warp w owns query rows w*16..+15.
// qkv layout: [b][3*C][HW]. grid = (49, 8, 2).
// ---------------------------------------------------------------------------
__global__ void __launch_bounds__(128)
attn_bf(const float* __restrict__ qkv, float* __restrict__ o) {
    const int qt = blockIdx.x;
    const int h  = blockIdx.y;
    const int b  = blockIdx.z;
    const float* qp = qkv + ((size_t)b * 3 * C + h * HD) * HW;
    const float* kp = qp + (size_t)C * HW;
    const float* vp = qp + (size_t)2 * C * HW;
    float* op = o + ((size_t)b * C + h * HD) * HW;

    __shared__ uint32_t Qs[16][72];   // [d2][q]  pairs along d
    __shared__ uint32_t Ks[16][72];   // [d2][p]  pairs along d
    __shared__ uint32_t Vsd[32][36];  // [d][p2]  pairs along p
    __shared__ uint32_t Ps[32][72];   // [p2][q]  pairs along p; reused as Os
    float* Osf = (float*)&Ps[0][0];   // [64][36] fp32 O staging

    const int tid  = threadIdx.x;
    const int lane = tid & 31;
    const int warp = tid >> 5;
    const int g    = lane >> 2;
    const int t4   = lane & 3;
    const int q0   = qt * 64;
    const int r0   = warp * 16 + g;
    const int r1   = r0 + 8;
    const float scale = 0.17677669529663687f;   // 1/sqrt(32)

    // Q tile: pairs along d, pre-scaled
    for (int i = tid; i < 256; i += 128) {
        int d2 = i >> 4, pq = (i & 15) * 4;
        const float* p0 = &qp[(size_t)(2 * d2) * HW + q0 + pq];
        float4 f0 = *(const float4*)p0;
        float4 f1 = *(const float4*)(p0 + HW);
        uint4 u;
        u.x = pk(f0.x * scale, f1.x * scale);
        u.y = pk(f0.y * scale, f1.y * scale);
        u.z = pk(f0.z * scale, f1.z * scale);
        u.w = pk(f0.w * scale, f1.w * scale);
        *(uint4*)&Qs[d2][pq] = u;
    }

    float m0 = -INFINITY, m1 = -INFINITY, l0 = 0.f, l1 = 0.f;
    float oacc[4][4];
#pragma unroll
    for (int i = 0; i < 4; i++)
#pragma unroll
        for (int j = 0; j < 4; j++) oacc[i][j] = 0.f;

    for (int kt = 0; kt < 49; kt++) {
        __syncthreads();
        // K tile: pairs along d
        for (int i = tid; i < 256; i += 128) {
            int d2 = i >> 4, pq = (i & 15) * 4;
            const float* p0 = &kp[(size_t)(2 * d2) * HW + kt * 64 + pq];
            float4 f0 = *(const float4*)p0;
            float4 f1 = *(const float4*)(p0 + HW);
            uint4 u;
            u.x = pk(f0.x, f1.x); u.y = pk(f0.y, f1.y);
            u.z = pk(f0.z, f1.z); u.w = pk(f0.w, f1.w);
            *(uint4*)&Ks[d2][pq] = u;
        }
        // V tile: d-major, pairs along p
        for (int i = tid; i < 512; i += 128) {
            int d = i >> 4, pq = i & 15;
            float4 f = *(const float4*)&vp[(size_t)d * HW + kt * 64 + pq * 4];
            uint2 u;
            u.x = pk(f.x, f.y);
            u.y = pk(f.z, f.w);
            *(uint2*)&Vsd[d][pq * 2] = u;
        }
        __syncthreads();

        // ---- S = Q K^T : 8 n-tiles x 2 k16-steps per warp ----
        float s[8][4];
#pragma unroll
        for (int nt = 0; nt < 8; nt++)
#pragma unroll
            for (int j = 0; j < 4; j++) s[nt][j] = 0.f;

#pragma unroll
        for (int ks = 0; ks < 2; ks++) {
            uint32_t a0 = Qs[ks * 8 + t4][r0];
            uint32_t a1 = Qs[ks * 8 + t4][r1];
            uint32_t a2 = Qs[ks * 8 + t4 + 4][r0];
            uint32_t a3 = Qs[ks * 8 + t4 + 4][r1];
#pragma unroll
            for (int nt = 0; nt < 8; nt++) {
                int p = nt * 8 + g;
                mma16(s[nt], a0, a1, a2, a3,
                      Ks[ks * 8 + t4][p], Ks[ks * 8 + t4 + 4][p]);
            }
        }

        // ---- online softmax on C-fragments ----
        float mx0 = -INFINITY, mx1 = -INFINITY;
#pragma unroll
        for (int nt = 0; nt < 8; nt++) {
            mx0 = fmaxf(mx0, fmaxf(s[nt][0], s[nt][1]));
            mx1 = fmaxf(mx1, fmaxf(s[nt][2], s[nt][3]));
        }
        mx0 = fmaxf(mx0, __shfl_xor_sync(0xffffffffu, mx0, 1));
        mx0 = fmaxf(mx0, __shfl_xor_sync(0xffffffffu, mx0, 2));
        mx1 = fmaxf(mx1, __shfl_xor_sync(0xffffffffu, mx1, 1));
        mx1 = fmaxf(mx1, __shfl_xor_sync(0xffffffffu, mx1, 2));

        float mn0 = fmaxf(m0, mx0);
        float mn1 = fmaxf(m1, mx1);
        float al0 = __expf(m0 - mn0);
        float al1 = __expf(m1 - mn1);
        m0 = mn0; m1 = mn1;

        float rs0 = 0.f, rs1 = 0.f;
#pragma unroll
        for (int nt = 0; nt < 8; nt++) {
            float p00 = __expf(s[nt][0] - mn0);
            float p01 = __expf(s[nt][1] - mn0);
            float p10 = __expf(s[nt][2] - mn1);
            float p11 = __expf(s[nt][3] - mn1);
            rs0 += p00 + p01;
            rs1 += p10 + p11;
            int p2 = nt * 4 + t4;               // cols (2*p2, 2*p2+1)
            Ps[p2][r0] = pk(p00, p01);
            Ps[p2][r1] = pk(p10, p11);
        }
        rs0 += __shfl_xor_sync(0xffffffffu, rs0, 1);
        rs0 += __shfl_xor_sync(0xffffffffu, rs0, 2);
        rs1 += __shfl_xor_sync(0xffffffffu, rs1, 1);
        rs1 += __shfl_xor_sync(0xffffffffu, rs1, 2);
        l0 = l0 * al0 + rs0;
        l1 = l1 * al1 + rs1;
#pragma unroll
        for (int nt = 0; nt < 4; nt++) {
            oacc[nt][0] *= al0; oacc[nt][1] *= al0;
            oacc[nt][2] *= al1; oacc[nt][3] *= al1;
        }
        __syncwarp();   // Ps columns are warp-private; order write->read

        // ---- O += P V : 4 k16-steps x 4 n-tiles per warp ----
#pragma unroll
        for (int ks = 0; ks < 4; ks++) {
            uint32_t a0 = Ps[ks * 8 + t4][r0];
            uint32_t a1 = Ps[ks * 8 + t4][r1];
            uint32_t a2 = Ps[ks * 8 + t4 + 4][r0];
            uint32_t a3 = Ps[ks * 8 + t4 + 4][r1];
#pragma unroll
            for (int nt = 0; nt < 4; nt++) {
                int d = nt * 8 + g;
                mma16(oacc[nt], a0, a1, a2, a3,
                      Vsd[d][ks * 8 + t4], Vsd[d][ks * 8 + t4 + 4]);
            }
        }
    }

    // ---- normalize + stage to smem (Os[q][36]) + coalesced store ----
    __syncthreads();
    float inv0 = 1.f / l0;
    float inv1 = 1.f / l1;
#pragma unroll
    for (int nt = 0; nt < 4; nt++) {
        int d0 = nt * 8 + 2 * t4;
        Osf[r0 * 36 + d0]     = oacc[nt][0] * inv0;
        Osf[r0 * 36 + d0 + 1] = oacc[nt][1] * inv0;
        Osf[r1 * 36 + d0]     = oacc[nt][2] * inv1;
        Osf[r1 * 36 + d0 + 1] = oacc[nt][3] * inv1;
    }
    __syncthreads();
    for (int i = tid; i < 2048; i += 128) {
        int d = i >> 6, p = i & 63;
        op[(size_t)d * HW + q0 + p] = Osf[p * 36 + d];
    }
}

// ---------------------------------------------------------------------------
// Launch
// ---------------------------------------------------------------------------
extern "C" void kernel_launch(void* const* d_in, const int* in_sizes, int n_in,
                              void* d_out, int out_size) {
    const float* x     = (const float*)d_in[0];
    const float* wq    = (const float*)d_in[1];
    const float* bq    = (const float*)d_in[2];
    const float* wk    = (const float*)d_in[3];
    const float* bk    = (const float*)d_in[4];
    const float* wv    = (const float*)d_in[5];
    const float* bv    = (const float*)d_in[6];
    const float* wo    = (const float*)d_in[7];
    const float* bo    = (const float*)d_in[8];
    const float* g1    = (const float*)d_in[9];
    const float* be1   = (const float*)d_in[10];
    const float* g2    = (const float*)d_in[11];
    const float* be2   = (const float*)d_in[12];
    const float* wm1   = (const float*)d_in[13];
    const float* bm1   = (const float*)d_in[14];
    const float* wm2   = (const float*)d_in[15];
    const float* bm2   = (const float*)d_in[16];
    float* out = (float*)d_out;

    float *s1, *t1, *s2, *t2, *bqkvf, *bm1f;
    uint32_t *wqkvt, *wot, *wm1t, *wm2t;
    float *qkvb, *ao, *x2, *hb;
    cudaGetSymbolAddress((void**)&s1, g_s1);
    cudaGetSymbolAddress((void**)&t1, g_t1);
    cudaGetSymbolAddress((void**)&s2, g_s2);
    cudaGetSymbolAddress((void**)&t2, g_t2);
    cudaGetSymbolAddress((void**)&wqkvt, g_wqkv_t);
    cudaGetSymbolAddress((void**)&bqkvf, g_bqkv);
    cudaGetSymbolAddress((void**)&wot, g_wo_t);
    cudaGetSymbolAddress((void**)&wm1t, g_wm1_t);
    cudaGetSymbolAddress((void**)&bm1f, g_bm1);
    cudaGetSymbolAddress((void**)&wm2t, g_wm2_t);
    cudaGetSymbolAddress((void**)&qkvb, g_qkv);
    cudaGetSymbolAddress((void**)&ao, g_ao);
    cudaGetSymbolAddress((void**)&x2, g_x2);
    cudaGetSymbolAddress((void**)&hb, g_h);

    // 1) BN1 stats + fold+pack stacked QKV weights; pack wo
    bn_stats_kernel<<<C, 256>>>(x, g1, be1, s1, t1);
    fold_bf<<<C, 128>>>(wq, bq, s1, t1, wqkvt, bqkvf, 768, 0);
    fold_bf<<<C, 128>>>(wk, bk, s1, t1, wqkvt, bqkvf, 768, 256);
    fold_bf<<<C, 128>>>(wv, bv, s1, t1, wqkvt, bqkvf, 768, 512);
    conv_w<<<128, 256>>>(wo, wot, 256, 256);

    // 2) fused QKV projection: M=768
    gemm_bf<0><<<dim3(HW / 64, 6, BATCH), 256>>>(wqkvt, x, bqkvf, nullptr, qkvb, 768, C, HW);

    // 3) bf16 flash attention
    attn_bf<<<dim3(HW / 64, HEADS, BATCH), 128>>>(qkvb, ao);

    // 4) output projection + residual -> x2
    gemm_bf<2><<<dim3(HW / 64, 2, BATCH), 256>>>(wot, ao, bo, x, x2, C, C, HW);

    // 5) BN2 stats + fold+pack MLP1; pack MLP2
    bn_stats_kernel<<<C, 256>>>(x2, g2, be2, s2, t2);
    fold_bf<<<C4, 128>>>(wm1, bm1, s2, t2, wm1t, bm1f, 1024, 0);
    conv_w<<<512, 256>>>(wm2, wm2t, 1024, 256);

    // 6) MLP1 (+ReLU)
    gemm_bf<1><<<dim3(HW / 64, 8, BATCH), 256>>>(wm1t, x2, bm1f, nullptr, hb, C4, C, HW);

    // 7) MLP2 + residual -> out
    gemm_bf<2><<<dim3(HW / 64, 2, BATCH), 256>>>(wm2t, hb, bm2, x2, out, C, C4, HW);
}

// round 8
// speedup vs baseline: 4.7719x; 1.1930x over previous
#include <cuda_runtime.h>
#include <cuda_bf16.h>
#include <math.h>
#include <stdint.h>

// Problem constants
#define BATCH 2
#define C 256
#define HW 3136          // 56*56
#define HEADS 8
#define HD 32
#define EPS 1e-5f
#define C4 (4*C)         // 1024

// ---------------------------------------------------------------------------
// Scratch (device globals; no allocation allowed)
// ---------------------------------------------------------------------------
__device__ float    g_s1[C], g_t1[C];
__device__ float    g_s2[C], g_t2[C];
__device__ uint32_t g_wqkv_t[128*768];   // bf16x2 pairs along K, [k2][M]
__device__ float    g_bqkv[768];
__device__ uint32_t g_wo_t[128*256];
__device__ uint32_t g_wm1_t[128*1024];
__device__ float    g_bm1[1024];
__device__ uint32_t g_wm2_t[512*256];
__device__ __nv_bfloat16 g_qkv16[BATCH*3*C*HW];
__device__ __nv_bfloat16 g_ao16[BATCH*C*HW];
__device__ float    g_x2[BATCH*C*HW];
__device__ __nv_bfloat16 g_h16[BATCH*C4*HW];

// ---------------------------------------------------------------------------
// helpers
// ---------------------------------------------------------------------------
__device__ __forceinline__ uint32_t pk(float lo, float hi) {
    uint32_t r;
    asm("cvt.rn.bf16x2.f32 %0, %1, %2;" : "=r"(r) : "f"(hi), "f"(lo));
    return r;
}
__device__ __forceinline__ uint32_t prmt(uint32_t a, uint32_t b, uint32_t sel) {
    uint32_t r;
    asm("prmt.b32 %0, %1, %2, %3;" : "=r"(r) : "r"(a), "r"(b), "r"(sel));
    return r;
}
__device__ __forceinline__ void mma16(float* d, uint32_t a0, uint32_t a1,
                                      uint32_t a2, uint32_t a3,
                                      uint32_t b0, uint32_t b1) {
    asm volatile(
        "mma.sync.aligned.m16n8k16.row.col.f32.bf16.bf16.f32 "
        "{%0,%1,%2,%3}, {%4,%5,%6,%7}, {%8,%9}, {%0,%1,%2,%3};"
        : "+f"(d[0]), "+f"(d[1]), "+f"(d[2]), "+f"(d[3])
        : "r"(a0), "r"(a1), "r"(a2), "r"(a3), "r"(b0), "r"(b1));
}

// ---------------------------------------------------------------------------
// BN stats: s = gamma*rsqrt(var+eps), t = beta - mean*s
// ---------------------------------------------------------------------------
__global__ void bn_stats_kernel(const float* __restrict__ x,
                                const float* __restrict__ gamma,
                                const float* __restrict__ beta,
                                float* __restrict__ s, float* __restrict__ t) {
    int c = blockIdx.x;
    int tid = threadIdx.x;
    float sum = 0.f, sq = 0.f;
    for (int b = 0; b < BATCH; b++) {
        const float* p = x + ((size_t)b * C + c) * HW;
        for (int i = tid; i < HW; i += blockDim.x) {
            float v = p[i];
            sum += v; sq += v * v;
        }
    }
    __shared__ float rs[256], rq[256];
    rs[tid] = sum; rq[tid] = sq;
    __syncthreads();
    for (int off = 128; off > 0; off >>= 1) {
        if (tid < off) { rs[tid] += rs[tid + off]; rq[tid] += rq[tid + off]; }
        __syncthreads();
    }
    if (tid == 0) {
        const float n = (float)(BATCH * HW);
        float mean = rs[0] / n;
        float var  = rq[0] / n - mean * mean;
        float sc = gamma[c] * rsqrtf(var + EPS);
        s[c] = sc;
        t[c] = beta[c] - mean * sc;
    }
}

// ---------------------------------------------------------------------------
// Fold BN into one conv weight; emit transposed bf16x2 [k2][Mtot] + bias.
// extra output scale `osc` folds softmax scale into Q. K fixed = 256.
// ---------------------------------------------------------------------------
__device__ __forceinline__ void fold_one(const float* w, const float* bias,
                                         const float* s, const float* t,
                                         uint32_t* wt, float* bf,
                                         int Mtot, int oo, int o, float osc, int p) {
    float w0 = w[(size_t)o * 256 + 2 * p];
    float w1 = w[(size_t)o * 256 + 2 * p + 1];
    float acc = w0 * t[2 * p] + w1 * t[2 * p + 1];
    wt[(size_t)p * Mtot + oo] = pk(w0 * s[2 * p] * osc, w1 * s[2 * p + 1] * osc);
    __shared__ float red[128];
    red[p] = acc;
    __syncthreads();
    for (int o2 = 64; o2 > 0; o2 >>= 1) {
        if (p < o2) red[p] += red[p + o2];
        __syncthreads();
    }
    if (p == 0) bf[oo] = (bias[o] + red[0]) * osc;
}

// fused QKV fold: grid 768 (q rows scaled by 1/sqrt(hd))
__global__ void fold_qkv(const float* __restrict__ wq, const float* __restrict__ bq,
                         const float* __restrict__ wk, const float* __restrict__ bk,
                         const float* __restrict__ wv, const float* __restrict__ bv,
                         const float* __restrict__ s, const float* __restrict__ t,
                         uint32_t* __restrict__ wt, float* __restrict__ bf) {
    int oo = blockIdx.x;
    int p = threadIdx.x;
    if (oo < 256)      fold_one(wq, bq, s, t, wt, bf, 768, oo, oo,       0.17677669529663687f, p);
    else if (oo < 512) fold_one(wk, bk, s, t, wt, bf, 768, oo, oo - 256, 1.f, p);
    else               fold_one(wv, bv, s, t, wt, bf, 768, oo, oo - 512, 1.f, p);
}

__global__ void fold_m1(const float* __restrict__ w, const float* __restrict__ bias,
                        const float* __restrict__ s, const float* __restrict__ t,
                        uint32_t* __restrict__ wt, float* __restrict__ bf) {
    fold_one(w, bias, s, t, wt, bf, 1024, blockIdx.x, blockIdx.x, 1.f, threadIdx.x);
}

// Pack weight (no fold): wt[p][o] = bf16x2(w[o][2p], w[o][2p+1]).
__global__ void conv_w(const float* __restrict__ w, uint32_t* __restrict__ wt,
                       int K, int M) {
    int p = blockIdx.x;
    for (int o = threadIdx.x; o < M; o += blockDim.x)
        wt[(size_t)p * M + o] = pk(w[(size_t)o * K + 2 * p],
                                   w[(size_t)o * K + 2 * p + 1]);
}

// ---------------------------------------------------------------------------
// bf16 tensor-core GEMM.  Wt: bf16x2 [K/2][M].  BM=128,BN=64,BK=32, 8 warps.
// EPI: 0 plain, 1 relu, 2 +residual(fp32).  INBF: B operand bf16.  OUTBF: out bf16.
// grid = (N/64, M/128, BATCH)
// ---------------------------------------------------------------------------
template<int EPI, int INBF, int OUTBF>
__global__ void __launch_bounds__(256)
gemm_bf(const uint32_t* __restrict__ Wt, const void* __restrict__ Bmv,
        const float* __restrict__ bias, const float* __restrict__ res,
        void* __restrict__ Coutv, int M, int K, int N) {
    __shared__ uint32_t As[2][16][136];
    __shared__ uint32_t Bs[2][16][72];

    const int bn = blockIdx.x;
    const int bm = blockIdx.y;
    const int batch = blockIdx.z;
    const float* Rp = (EPI == 2) ? (res + (size_t)batch * M * N) : nullptr;

    const int tid = threadIdx.x;
    const int lane = tid & 31;
    const int wid = tid >> 5;
    const int warp_m = wid & 3;
    const int warp_n = wid >> 2;
    const int g = lane >> 2;
    const int t4 = lane & 3;

    float acc[2][4][4];
#pragma unroll
    for (int i = 0; i < 2; i++)
#pragma unroll
        for (int j = 0; j < 4; j++)
#pragma unroll
            for (int k = 0; k < 4; k++) acc[i][j][k] = 0.f;

    const int a_k2 = tid >> 5;
    const int a_m  = (tid & 31) * 4;
    const int b_k2 = tid >> 4;
    const int b_n  = (tid & 15) * 4;

    uint4 aR0, aR1;
    float4 bR0, bR1;           // INBF=0
    uint2 bU0, bU1;            // INBF=1

    const float* BpF = (const float*)Bmv + (INBF ? 0 : (size_t)batch * K * N);
    const __nv_bfloat16* BpH = (const __nv_bfloat16*)Bmv + (INBF ? (size_t)batch * K * N : 0);

#define LDG_T(K2B)                                                                   \
    do {                                                                             \
        aR0 = *(const uint4*)&Wt[(size_t)((K2B) + a_k2) * M + bm * 128 + a_m];       \
        aR1 = *(const uint4*)&Wt[(size_t)((K2B) + a_k2 + 8) * M + bm * 128 + a_m];   \
        if (INBF) {                                                                  \
            const __nv_bfloat16* bp = &BpH[(size_t)(2 * (K2B) + 2 * b_k2) * N + bn * 64 + b_n]; \
            bU0 = *(const uint2*)bp;                                                 \
            bU1 = *(const uint2*)(bp + N);                                           \
        } else {                                                                     \
            const float* bp = &BpF[(size_t)(2 * (K2B) + 2 * b_k2) * N + bn * 64 + b_n]; \
            bR0 = *(const float4*)bp;                                                \
            bR1 = *(const float4*)(bp + N);                                          \
        }                                                                            \
    } while (0)

#define STS_T(BUF)                                                                   \
    do {                                                                             \
        *(uint4*)&As[BUF][a_k2][a_m] = aR0;                                          \
        *(uint4*)&As[BUF][a_k2 + 8][a_m] = aR1;                                      \
        uint4 bb;                                                                    \
        if (INBF) {                                                                  \
            bb.x = prmt(bU0.x, bU1.x, 0x5410); bb.y = prmt(bU0.x, bU1.x, 0x7632);    \
            bb.z = prmt(bU0.y, bU1.y, 0x5410); bb.w = prmt(bU0.y, bU1.y, 0x7632);    \
        } else {                                                                     \
            bb.x = pk(bR0.x, bR1.x); bb.y = pk(bR0.y, bR1.y);                        \
            bb.z = pk(bR0.z, bR1.z); bb.w = pk(bR0.w, bR1.w);                        \
        }                                                                            \
        *(uint4*)&Bs[BUF][b_k2][b_n] = bb;                                           \
    } while (0)

    const int iters = K >> 5;
    LDG_T(0);
    STS_T(0);
    __syncthreads();

    for (int it = 0; it < iters; ++it) {
        if (it + 1 < iters) LDG_T((it + 1) * 16);
        const int buf = it & 1;
#pragma unroll
        for (int ks = 0; ks < 2; ks++) {
            uint32_t a[2][4];
#pragma unroll
            for (int mm = 0; mm < 2; mm++) {
                int r = warp_m * 32 + mm * 16 + g;
                a[mm][0] = As[buf][ks * 8 + t4][r];
                a[mm][1] = As[buf][ks * 8 + t4][r + 8];
                a[mm][2] = As[buf][ks * 8 + t4 + 4][r];
                a[mm][3] = As[buf][ks * 8 + t4 + 4][r + 8];
            }
#pragma unroll
            for (int nt = 0; nt < 4; nt++) {
                int n = warp_n * 32 + nt * 8 + g;
                uint32_t b0 = Bs[buf][ks * 8 + t4][n];
                uint32_t b1 = Bs[buf][ks * 8 + t4 + 4][n];
                mma16(acc[0][nt], a[0][0], a[0][1], a[0][2], a[0][3], b0, b1);
                mma16(acc[1][nt], a[1][0], a[1][1], a[1][2], a[1][3], b0, b1);
            }
        }
        if (it + 1 < iters) {
            STS_T((it + 1) & 1);
            __syncthreads();
        }
    }

    float* CpF = (float*)Coutv + (OUTBF ? 0 : (size_t)batch * M * N);
    __nv_bfloat16* CpH = (__nv_bfloat16*)Coutv + (OUTBF ? (size_t)batch * M * N : 0);

#pragma unroll
    for (int mm = 0; mm < 2; mm++) {
        int r0 = bm * 128 + warp_m * 32 + mm * 16 + g;
        float bv0 = bias[r0];
        float bv1 = bias[r0 + 8];
#pragma unroll
        for (int nt = 0; nt < 4; nt++) {
            int col = bn * 64 + warp_n * 32 + nt * 8 + t4 * 2;
            float2 v0 = make_float2(acc[mm][nt][0] + bv0, acc[mm][nt][1] + bv0);
            float2 v1 = make_float2(acc[mm][nt][2] + bv1, acc[mm][nt][3] + bv1);
            if (EPI == 1) {
                v0.x = fmaxf(v0.x, 0.f); v0.y = fmaxf(v0.y, 0.f);
                v1.x = fmaxf(v1.x, 0.f); v1.y = fmaxf(v1.y, 0.f);
            }
            if (EPI == 2) {
                float2 r0v = *(const float2*)&Rp[(size_t)r0 * N + col];
                float2 r1v = *(const float2*)&Rp[(size_t)(r0 + 8) * N + col];
                v0.x += r0v.x; v0.y += r0v.y;
                v1.x += r1v.x; v1.y += r1v.y;
            }
            if (OUTBF) {
                *(uint32_t*)&CpH[(size_t)r0 * N + col] = pk(v0.x, v0.y);
                *(uint32_t*)&CpH[(size_t)(r0 + 8) * N + col] = pk(v1.x, v1.y);
            } else {
                *(float2*)&CpF[(size_t)r0 * N + col] = v0;
                *(float2*)&CpF[(size_t)(r0 + 8) * N + col] = v1;
            }
        }
    }
#undef LDG_T
#undef STS_T
}

// ---------------------------------------------------------------------------
// bf16 flash attention, 128 queries/block, 256 threads = 8 warps.
// Input qkv bf16 [b][3C][HW] (Q pre-scaled via weight fold). Output ao bf16.
// grid = (ceil(HW/128), 8, 2).
// ---------------------------------------------------------------------------
__global__ void __launch_bounds__(256)
attn_bf(const __nv_bfloat16* __restrict__ qkv, __nv_bfloat16* __restrict__ o) {
    const int qt = blockIdx.x;
    const int h  = blockIdx.y;
    const int b  = blockIdx.z;
    const __nv_bfloat16* qp = qkv + ((size_t)b * 3 * C + h * HD) * HW;
    const __nv_bfloat16* kp = qp + (size_t)C * HW;
    const __nv_bfloat16* vp = qp + (size_t)2 * C * HW;
    __nv_bfloat16* op = o + ((size_t)b * C + h * HD) * HW;

    __shared__ uint32_t Qs[16][136];  // [d2][q] pairs along d, 128 q
    __shared__ uint32_t Ks[16][72];   // [d2][p] pairs along d, 64 p
    __shared__ uint32_t Vsd[32][36];  // [d][p2] pairs along p
    __shared__ uint32_t Ps[32][136];  // [p2][q] pairs along p; reused as Os
    float* Osf = (float*)&Ps[0][0];   // [128][34] fp32 O staging (17408 B fits)

    const int tid  = threadIdx.x;
    const int lane = tid & 31;
    const int warp = tid >> 5;
    const int g    = lane >> 2;
    const int t4   = lane & 3;
    const int q0   = qt * 128;
    const int r0   = warp * 16 + g;
    const int r1   = r0 + 8;

    // Q tile: 16 d2 x 128 q; one uint4-pair per thread (8 q each)
    {
        int d2 = tid >> 4;
        int qc = (tid & 15) * 8;
        int qcc = min(qc, HW - 8 - q0);          // tail clamp
        const __nv_bfloat16* p0 = &qp[(size_t)(2 * d2) * HW + q0 + qcc];
        uint4 a = *(const uint4*)p0;
        uint4 c = *(const uint4*)(p0 + HW);
        uint4 u0, u1;
        u0.x = prmt(a.x, c.x, 0x5410); u0.y = prmt(a.x, c.x, 0x7632);
        u0.z = prmt(a.y, c.y, 0x5410); u0.w = prmt(a.y, c.y, 0x7632);
        u1.x = prmt(a.z, c.z, 0x5410); u1.y = prmt(a.z, c.z, 0x7632);
        u1.z = prmt(a.w, c.w, 0x5410); u1.w = prmt(a.w, c.w, 0x7632);
        *(uint4*)&Qs[d2][qc] = u0;
        *(uint4*)&Qs[d2][qc + 4] = u1;
    }

    float m0 = -INFINITY, m1 = -INFINITY, l0 = 0.f, l1 = 0.f;
    float oacc[4][4];
#pragma unroll
    for (int i = 0; i < 4; i++)
#pragma unroll
        for (int j = 0; j < 4; j++) oacc[i][j] = 0.f;

    for (int kt = 0; kt < 49; kt++) {
        __syncthreads();
        // K tile: 16 d2 x 64 p (128 active threads)
        if (tid < 128) {
            int d2 = tid >> 3;
            int pc = (tid & 7) * 8;
            const __nv_bfloat16* p0 = &kp[(size_t)(2 * d2) * HW + kt * 64 + pc];
            uint4 a = *(const uint4*)p0;
            uint4 c = *(const uint4*)(p0 + HW);
            uint4 u0, u1;
            u0.x = prmt(a.x, c.x, 0x5410); u0.y = prmt(a.x, c.x, 0x7632);
            u0.z = prmt(a.y, c.y, 0x5410); u0.w = prmt(a.y, c.y, 0x7632);
            u1.x = prmt(a.z, c.z, 0x5410); u1.y = prmt(a.z, c.z, 0x7632);
            u1.z = prmt(a.w, c.w, 0x5410); u1.w = prmt(a.w, c.w, 0x7632);
            *(uint4*)&Ks[d2][pc] = u0;
            *(uint4*)&Ks[d2][pc + 4] = u1;
        } else {
            // V tile: 32 d x 64 p; adjacent p already pairs in memory
            int i = tid - 128;                   // 0..127, 4 p-pairs each... 2 iters
#pragma unroll
            for (int it2 = 0; it2 < 2; it2++) {
                int j = i + it2 * 128;           // 0..255
                int d = j >> 3;
                int pc2 = (j & 7) * 4;           // p2 offset
                uint4 v = *(const uint4*)&vp[(size_t)d * HW + kt * 64 + pc2 * 2];
                *(uint4*)&Vsd[d][pc2] = v;
            }
        }
        __syncthreads();

        // ---- S = Q K^T ----
        float s[8][4];
#pragma unroll
        for (int nt = 0; nt < 8; nt++)
#pragma unroll
            for (int j = 0; j < 4; j++) s[nt][j] = 0.f;

#pragma unroll
        for (int ks = 0; ks < 2; ks++) {
            uint32_t a0 = Qs[ks * 8 + t4][r0];
            uint32_t a1 = Qs[ks * 8 + t4][r1];
            uint32_t a2 = Qs[ks * 8 + t4 + 4][r0];
            uint32_t a3 = Qs[ks * 8 + t4 + 4][r1];
#pragma unroll
            for (int nt = 0; nt < 8; nt++) {
                int p = nt * 8 + g;
                mma16(s[nt], a0, a1, a2, a3,
                      Ks[ks * 8 + t4][p], Ks[ks * 8 + t4 + 4][p]);
            }
        }

        // ---- online softmax ----
        float mx0 = -INFINITY, mx1 = -INFINITY;
#pragma unroll
        for (int nt = 0; nt < 8; nt++) {
            mx0 = fmaxf(mx0, fmaxf(s[nt][0], s[nt][1]));
            mx1 = fmaxf(mx1, fmaxf(s[nt][2], s[nt][3]));
        }
        mx0 = fmaxf(mx0, __shfl_xor_sync(0xffffffffu, mx0, 1));
        mx0 = fmaxf(mx0, __shfl_xor_sync(0xffffffffu, mx0, 2));
        mx1 = fmaxf(mx1, __shfl_xor_sync(0xffffffffu, mx1, 1));
        mx1 = fmaxf(mx1, __shfl_xor_sync(0xffffffffu, mx1, 2));

        float mn0 = fmaxf(m0, mx0);
        float mn1 = fmaxf(m1, mx1);
        float al0 = __expf(m0 - mn0);
        float al1 = __expf(m1 - mn1);
        m0 = mn0; m1 = mn1;

        float rs0 = 0.f, rs1 = 0.f;
#pragma unroll
        for (int nt = 0; nt < 8; nt++) {
            float p00 = __expf(s[nt][0] - mn0);
            float p01 = __expf(s[nt][1] - mn0);
            float p10 = __expf(s[nt][2] - mn1);
            float p11 = __expf(s[nt][3] - mn1);
            rs0 += p00 + p01;
            rs1 += p10 + p11;
            int p2 = nt * 4 + t4;
            Ps[p2][r0] = pk(p00, p01);
            Ps[p2][r1] = pk(p10, p11);
        }
        rs0 += __shfl_xor_sync(0xffffffffu, rs0, 1);
        rs0 += __shfl_xor_sync(0xffffffffu, rs0, 2);
        rs1 += __shfl_xor_sync(0xffffffffu, rs1, 1);
        rs1 += __shfl_xor_sync(0xffffffffu, rs1, 2);
        l0 = l0 * al0 + rs0;
        l1 = l1 * al1 + rs1;
#pragma unroll
        for (int nt = 0; nt < 4; nt++) {
            oacc[nt][0] *= al0; oacc[nt][1] *= al0;
            oacc[nt][2] *= al1; oacc[nt][3] *= al1;
        }
        __syncwarp();

        // ---- O += P V ----
#pragma unroll
        for (int ks = 0; ks < 4; ks++) {
            uint32_t a0 = Ps[ks * 8 + t4][r0];
            uint32_t a1 = Ps[ks * 8 + t4][r1];
            uint32_t a2 = Ps[ks * 8 + t4 + 4][r0];
            uint32_t a3 = Ps[ks * 8 + t4 + 4][r1];
#pragma unroll
            for (int nt = 0; nt < 4; nt++) {
                int d = nt * 8 + g;
                mma16(oacc[nt], a0, a1, a2, a3,
                      Vsd[d][ks * 8 + t4], Vsd[d][ks * 8 + t4 + 4]);
            }
        }
    }

    // ---- normalize + stage (Os[q][34]) + bf16 store ----
    __syncthreads();
    float inv0 = 1.f / l0;
    float inv1 = 1.f / l1;
#pragma unroll
    for (int nt = 0; nt < 4; nt++) {
        int d0 = nt * 8 + 2 * t4;
        Osf[r0 * 34 + d0]     = oacc[nt][0] * inv0;
        Osf[r0 * 34 + d0 + 1] = oacc[nt][1] * inv0;
        Osf[r1 * 34 + d0]     = oacc[nt][2] * inv1;
        Osf[r1 * 34 + d0 + 1] = oacc[nt][3] * inv1;
    }
    __syncthreads();
    for (int i = tid; i < 2048; i += 256) {
        int d = i >> 6, p2 = i & 63;
        int p = 2 * p2;
        if (q0 + p + 1 < HW) {
            uint32_t v = pk(Osf[p * 34 + d], Osf[(p + 1) * 34 + d]);
            *(uint32_t*)&op[(size_t)d * HW + q0 + p] = v;
        }
    }
}

// ---------------------------------------------------------------------------
// Launch
// ---------------------------------------------------------------------------
extern "C" void kernel_launch(void* const* d_in, const int* in_sizes, int n_in,
                              void* d_out, int out_size) {
    const float* x     = (const float*)d_in[0];
    const float* wq    = (const float*)d_in[1];
    const float* bq    = (const float*)d_in[2];
    const float* wk    = (const float*)d_in[3];
    const float* bk    = (const float*)d_in[4];
    const float* wv    = (const float*)d_in[5];
    const float* bv    = (const float*)d_in[6];
    const float* wo    = (const float*)d_in[7];
    const float* bo    = (const float*)d_in[8];
    const float* g1    = (const float*)d_in[9];
    const float* be1   = (const float*)d_in[10];
    const float* g2    = (const float*)d_in[11];
    const float* be2   = (const float*)d_in[12];
    const float* wm1   = (const float*)d_in[13];
    const float* bm1   = (const float*)d_in[14];
    const float* wm2   = (const float*)d_in[15];
    const float* bm2   = (const float*)d_in[16];
    float* out = (float*)d_out;

    float *s1, *t1, *s2, *t2, *bqkvf, *bm1f, *x2;
    uint32_t *wqkvt, *wot, *wm1t, *wm2t;
    __nv_bfloat16 *qkvb, *aob, *hb;
    cudaGetSymbolAddress((void**)&s1, g_s1);
    cudaGetSymbolAddress((void**)&t1, g_t1);
    cudaGetSymbolAddress((void**)&s2, g_s2);
    cudaGetSymbolAddress((void**)&t2, g_t2);
    cudaGetSymbolAddress((void**)&wqkvt, g_wqkv_t);
    cudaGetSymbolAddress((void**)&bqkvf, g_bqkv);
    cudaGetSymbolAddress((void**)&wot, g_wo_t);
    cudaGetSymbolAddress((void**)&wm1t, g_wm1_t);
    cudaGetSymbolAddress((void**)&bm1f, g_bm1);
    cudaGetSymbolAddress((void**)&wm2t, g_wm2_t);
    cudaGetSymbolAddress((void**)&qkvb, g_qkv16);
    cudaGetSymbolAddress((void**)&aob, g_ao16);
    cudaGetSymbolAddress((void**)&x2, g_x2);
    cudaGetSymbolAddress((void**)&hb, g_h16);

    // weight packs independent of data
    conv_w<<<128, 256>>>(wo, wot, 256, 256);
    conv_w<<<512, 256>>>(wm2, wm2t, 1024, 256);

    // 1) BN1 stats + fused QKV fold (Q scale folded)
    bn_stats_kernel<<<C, 256>>>(x, g1, be1, s1, t1);
    fold_qkv<<<768, 128>>>(wq, bq, wk, bk, wv, bv, s1, t1, wqkvt, bqkvf);

    // 2) fused QKV projection -> bf16
    gemm_bf<0,0,1><<<dim3(HW / 64, 6, BATCH), 256>>>(wqkvt, x, bqkvf, nullptr, qkvb, 768, C, HW);

    // 3) flash attention (128 q/block) -> bf16
    attn_bf<<<dim3((HW + 127) / 128, HEADS, BATCH), 256>>>(qkvb, aob);

    // 4) output projection (bf16 in) + residual -> x2 fp32
    gemm_bf<2,1,0><<<dim3(HW / 64, 2, BATCH), 256>>>(wot, aob, bo, x, x2, C, C, HW);

    // 5) BN2 stats + MLP1 fold
    bn_stats_kernel<<<C, 256>>>(x2, g2, be2, s2, t2);
    fold_m1<<<C4, 128>>>(wm1, bm1, s2, t2, wm1t, bm1f);

    // 6) MLP1 (+ReLU) -> bf16 h
    gemm_bf<1,0,1><<<dim3(HW / 64, 8, BATCH), 256>>>(wm1t, x2, bm1f, nullptr, hb, C4, C, HW);

    // 7) MLP2 (bf16 in) + residual -> out fp32
    gemm_bf<2,1,0><<<dim3(HW / 64, 2, BATCH), 256>>>(wm2t, hb, bm2, x2, out, C, C4, HW);
}